// round 1
// baseline (speedup 1.0000x reference)
#include <cuda_runtime.h>
#include <cstdint>

// Problem constants
#define G_   64
#define NPG_ 400
#define N_   25600          // G_*NPG_
#define DEG_ 40
#define E_   1024000        // N_*DEG_
#define EMB_ 16
#define HID_ 192
#define OUTC_ 128
#define MODEL_ 64
#define DEMO_ 5

// ---------------- device scratch (no allocations allowed) ----------------
__device__ float g_deg[N_];
__device__ float g_dis[N_];
__device__ float g_norm[E_];
__device__ int   g_counts[N_];
__device__ int   g_rowptr[N_ + 1];
__device__ int   g_cursor[N_];
__device__ int2  g_csr[E_];            // .x = src local, .y = norm bits
__device__ float g_x0 [N_ * EMB_];
__device__ float g_t10[N_ * EMB_];
__device__ float g_t20[N_ * EMB_];
__device__ float g_xa [N_ * HID_];
__device__ float g_xb [N_ * HID_];
__device__ float g_t1 [N_ * HID_];
__device__ float g_t2 [N_ * HID_];
__device__ float g_gfeat[G_ * OUTC_];

// ---------------- preprocessing ----------------
__global__ void k_deg(const int* __restrict__ src, const float* __restrict__ ea) {
    int i = blockIdx.x * blockDim.x + threadIdx.x;
    if (i < E_) atomicAdd(&g_deg[src[i]], ea[i]);
}

__global__ void k_dis() {
    int i = blockIdx.x * blockDim.x + threadIdx.x;
    if (i < N_) {
        float d = g_deg[i];
        float r = 0.f;
        if (d > 0.f) {
            r = rsqrtf(d);
            r = r * (1.5f - 0.5f * d * r * r);   // Newton refine
        }
        g_dis[i] = r;
    }
}

__global__ void k_norm(const int* __restrict__ src, const int* __restrict__ dst,
                       const float* __restrict__ ea) {
    int i = blockIdx.x * blockDim.x + threadIdx.x;
    if (i < E_) {
        int s = src[i], t = dst[i];
        g_norm[i] = -g_dis[s] * ea[i] * g_dis[t];
        atomicAdd(&g_counts[t], 1);
    }
}

// per-graph exclusive scan of 400 in-degree counts -> rowptr, cursor
__global__ void k_scan() {
    __shared__ int s[NPG_];
    int g = blockIdx.x, t = threadIdx.x;
    int v = 0;
    if (t < NPG_) { v = g_counts[g * NPG_ + t]; s[t] = v; }
    __syncthreads();
    for (int off = 1; off < NPG_; off <<= 1) {
        int x = 0;
        if (t < NPG_ && t >= off) x = s[t - off];
        __syncthreads();
        if (t < NPG_) s[t] += x;
        __syncthreads();
    }
    if (t < NPG_) {
        int excl = g * (NPG_ * DEG_) + s[t] - v;
        g_rowptr[g * NPG_ + t] = excl;
        g_cursor[g * NPG_ + t] = excl;
    }
    if (g == 0 && t == 0) g_rowptr[N_] = E_;
}

__global__ void k_scatter(const int* __restrict__ src, const int* __restrict__ dst) {
    int i = blockIdx.x * blockDim.x + threadIdx.x;
    if (i < E_) {
        int t = dst[i];
        int p = atomicAdd(&g_cursor[t], 1);
        int sl = src[i] % NPG_;                 // src local within its graph
        g_csr[p] = make_int2(sl, __float_as_int(g_norm[i]));
    }
}

__global__ void k_embed(const int* __restrict__ ids, const float* __restrict__ emb) {
    int i = blockIdx.x * blockDim.x + threadIdx.x;
    if (i < N_ * EMB_) {
        int n = i >> 4, c = i & 15;
        g_x0[i] = emb[ids[n] * EMB_ + c];
    }
}

// ---------------- propagation: out = alpha * (A_norm @ h) + beta * bsrc ----------------
// One CTA = (graph, D-channel chunk). h chunk staged in SMEM; CSR-by-dst so each
// (node, channel) output is owned by one thread -> no atomics.
template <int D>
__global__ void k_prop(const float* __restrict__ h, int dtot,
                       const float* __restrict__ bsrc,
                       float* __restrict__ out,
                       float alpha, float beta) {
    extern __shared__ float hs[];           // NPG_ * D floats
    const int g  = blockIdx.x;
    const int cb = blockIdx.y * D;
    const int tid = threadIdx.x;

    const float* hb = h + (size_t)g * NPG_ * dtot + cb;
    for (int i = tid; i < NPG_ * D; i += blockDim.x) {
        int n = i / D, c = i % D;           // D is power of two
        hs[i] = hb[n * dtot + c];
    }
    __syncthreads();

    constexpr int LPN = D / 2;              // lanes per node (float2 per lane)
    const int sub   = tid % LPN;
    const int n0    = tid / LPN;
    const int nstep = blockDim.x / LPN;
    const int c     = 2 * sub;

    for (int n = n0; n < NPG_; n += nstep) {
        const int node = g * NPG_ + n;
        const int beg = g_rowptr[node];
        const int end = g_rowptr[node + 1];
        float ax = 0.f, ay = 0.f;
        int e = beg;
        for (; e + 2 <= end; e += 2) {
            int2 p0 = g_csr[e];
            int2 p1 = g_csr[e + 1];
            float w0 = __int_as_float(p0.y);
            float w1 = __int_as_float(p1.y);
            float2 h0 = *reinterpret_cast<const float2*>(&hs[p0.x * D + c]);
            float2 h1 = *reinterpret_cast<const float2*>(&hs[p1.x * D + c]);
            ax = fmaf(w0, h0.x, ax);  ay = fmaf(w0, h0.y, ay);
            ax = fmaf(w1, h1.x, ax);  ay = fmaf(w1, h1.y, ay);
        }
        for (; e < end; ++e) {
            int2 p = g_csr[e];
            float w = __int_as_float(p.y);
            float2 hv = *reinterpret_cast<const float2*>(&hs[p.x * D + c]);
            ax = fmaf(w, hv.x, ax);  ay = fmaf(w, hv.y, ay);
        }
        float ox = alpha * ax, oy = alpha * ay;
        if (bsrc != nullptr) {
            const float* bp = bsrc + (size_t)node * dtot + cb + c;
            ox = fmaf(beta, bp[0], ox);
            oy = fmaf(beta, bp[1], oy);
        }
        float* op = out + (size_t)node * dtot + cb + c;
        op[0] = ox;  op[1] = oy;
    }
}

// ---------------- fp32 GEMM: C[N_ x dout] = (accum ? C : bias) + A[N_ x kdim] @ W[kdim x dout]
// 128x64 tile, BK=16, 256 threads, 8x4 register microtile.
__global__ void k_gemm(const float* __restrict__ A, int kdim,
                       const float* __restrict__ W, int dout,
                       float* __restrict__ C,
                       const float* __restrict__ bias, int accum) {
    __shared__ float As[16][132];   // [k][m], padded
    __shared__ float Bs[16][64];    // [k][n]
    const int row0 = blockIdx.x * 128;
    const int col0 = blockIdx.y * 64;
    const int tid = threadIdx.x;
    const int tx = tid & 15;        // col group (4 cols)
    const int ty = tid >> 4;        // row group (8 rows)

    float acc[8][4];
    #pragma unroll
    for (int i = 0; i < 8; ++i)
        #pragma unroll
        for (int j = 0; j < 4; ++j) acc[i][j] = 0.f;

    const int am = tid >> 1;
    const int ako = (tid & 1) * 8;
    const int bk = tid >> 4;
    const int bc = (tid & 15) * 4;

    for (int kt = 0; kt < kdim; kt += 16) {
        const float* ap = A + (size_t)(row0 + am) * kdim + kt + ako;
        float4 av0 = *reinterpret_cast<const float4*>(ap);
        float4 av1 = *reinterpret_cast<const float4*>(ap + 4);
        As[ako + 0][am] = av0.x; As[ako + 1][am] = av0.y;
        As[ako + 2][am] = av0.z; As[ako + 3][am] = av0.w;
        As[ako + 4][am] = av1.x; As[ako + 5][am] = av1.y;
        As[ako + 6][am] = av1.z; As[ako + 7][am] = av1.w;

        float4 bv = *reinterpret_cast<const float4*>(W + (size_t)(kt + bk) * dout + col0 + bc);
        *reinterpret_cast<float4*>(&Bs[bk][bc]) = bv;
        __syncthreads();

        #pragma unroll
        for (int k = 0; k < 16; ++k) {
            float4 a0 = *reinterpret_cast<const float4*>(&As[k][ty * 8]);
            float4 a1 = *reinterpret_cast<const float4*>(&As[k][ty * 8 + 4]);
            float4 bb = *reinterpret_cast<const float4*>(&Bs[k][tx * 4]);
            float a[8] = {a0.x, a0.y, a0.z, a0.w, a1.x, a1.y, a1.z, a1.w};
            float b[4] = {bb.x, bb.y, bb.z, bb.w};
            #pragma unroll
            for (int i = 0; i < 8; ++i)
                #pragma unroll
                for (int j = 0; j < 4; ++j)
                    acc[i][j] = fmaf(a[i], b[j], acc[i][j]);
        }
        __syncthreads();
    }

    #pragma unroll
    for (int i = 0; i < 8; ++i) {
        int r = row0 + ty * 8 + i;
        float* cp = C + (size_t)r * dout + col0 + tx * 4;
        float4 prev;
        if (accum) {
            prev = *reinterpret_cast<const float4*>(cp);
        } else {
            prev.x = bias[col0 + tx * 4 + 0];
            prev.y = bias[col0 + tx * 4 + 1];
            prev.z = bias[col0 + tx * 4 + 2];
            prev.w = bias[col0 + tx * 4 + 3];
        }
        prev.x += acc[i][0]; prev.y += acc[i][1];
        prev.z += acc[i][2]; prev.w += acc[i][3];
        *reinterpret_cast<float4*>(cp) = prev;
    }
}

// ---------------- pooling + classifier ----------------
__global__ void k_pool(const float* __restrict__ x) {
    int g = blockIdx.x, c = threadIdx.x;     // 128 threads
    const float* p = x + (size_t)g * NPG_ * OUTC_ + c;
    float s = 0.f;
    for (int n = 0; n < NPG_; ++n) s += p[n * OUTC_];
    g_gfeat[g * OUTC_ + c] = s * (1.0f / NPG_);
}

__global__ void k_cls(const float* __restrict__ demo,
                      const float* __restrict__ w1, const float* __restrict__ b1,
                      const float* __restrict__ w2, const float* __restrict__ b2,
                      float* __restrict__ out) {
    __shared__ float f[OUTC_ + DEMO_];
    __shared__ float h[MODEL_];
    int g = blockIdx.x, m = threadIdx.x;     // 64 threads
    f[m] = g_gfeat[g * OUTC_ + m];
    f[64 + m] = g_gfeat[g * OUTC_ + 64 + m];
    if (m < DEMO_) f[OUTC_ + m] = demo[g * DEMO_ + m];
    __syncthreads();
    float acc = b1[m];
    for (int j = 0; j < OUTC_ + DEMO_; ++j)
        acc = fmaf(f[j], w1[j * MODEL_ + m], acc);
    h[m] = fmaxf(acc, 0.f);
    __syncthreads();
    if (m < 2) {
        float a = b2[m];
        for (int k = 0; k < MODEL_; ++k)
            a = fmaf(h[k], w2[k * 2 + m], a);
        out[g * 2 + m] = a;
    }
}

// ---------------- launcher ----------------
extern "C" void kernel_launch(void* const* d_in, const int* in_sizes, int n_in,
                              void* d_out, int out_size) {
    const int*   node_ids = (const int*)  d_in[0];
    const int*   eidx     = (const int*)  d_in[1];
    const float* eattr    = (const float*)d_in[3];
    const float* demo     = (const float*)d_in[4];
    const float* emb      = (const float*)d_in[5];
    const float* W0       = (const float*)d_in[6];
    const float* b0       = (const float*)d_in[7];
    const float* W1       = (const float*)d_in[8];
    const float* b1c      = (const float*)d_in[9];
    const float* W2       = (const float*)d_in[10];
    const float* b2c      = (const float*)d_in[11];
    const float* cw1      = (const float*)d_in[12];
    const float* cb1      = (const float*)d_in[13];
    const float* cw2      = (const float*)d_in[14];
    const float* cb2      = (const float*)d_in[15];
    float* out = (float*)d_out;

    const int* src = eidx;
    const int* dst = eidx + E_;

    // resolve device-global scratch
    float *p_deg, *p_x0, *p_t10, *p_t20, *p_xa, *p_xb, *p_t1, *p_t2;
    int *p_counts;
    cudaGetSymbolAddress((void**)&p_deg,    g_deg);
    cudaGetSymbolAddress((void**)&p_counts, g_counts);
    cudaGetSymbolAddress((void**)&p_x0,  g_x0);
    cudaGetSymbolAddress((void**)&p_t10, g_t10);
    cudaGetSymbolAddress((void**)&p_t20, g_t20);
    cudaGetSymbolAddress((void**)&p_xa,  g_xa);
    cudaGetSymbolAddress((void**)&p_xb,  g_xb);
    cudaGetSymbolAddress((void**)&p_t1,  g_t1);
    cudaGetSymbolAddress((void**)&p_t2,  g_t2);

    cudaFuncSetAttribute(k_prop<64>, cudaFuncAttributeMaxDynamicSharedMemorySize,
                         NPG_ * 64 * (int)sizeof(float));

    const int TB = 256;
    const int EB = E_ / TB;       // 4000
    const int NB = (N_ + TB - 1) / TB;

    // preprocessing
    cudaMemsetAsync(p_deg, 0, N_ * sizeof(float), 0);
    cudaMemsetAsync(p_counts, 0, N_ * sizeof(int), 0);
    k_deg<<<EB, TB>>>(src, eattr);
    k_dis<<<NB, TB>>>();
    k_norm<<<EB, TB>>>(src, dst, eattr);
    k_scan<<<G_, 512>>>();
    k_scatter<<<EB, TB>>>(src, dst);
    k_embed<<<(N_ * EMB_) / TB, TB>>>(node_ids, emb);

    const size_t smem16 = NPG_ * 16 * sizeof(float);
    const size_t smem64 = NPG_ * 64 * sizeof(float);

    // ---- layer 0: 16 -> 192 ----
    k_prop<16><<<dim3(G_, 1), TB, smem16>>>(p_x0, EMB_, nullptr, p_t10, 1.f, 0.f);
    k_prop<16><<<dim3(G_, 1), TB, smem16>>>(p_t10, EMB_, p_x0, p_t20, 2.f, -1.f);
    k_gemm<<<dim3(N_ / 128, HID_ / 64), TB>>>(p_x0,  EMB_, W0,                 HID_, p_xa, b0, 0);
    k_gemm<<<dim3(N_ / 128, HID_ / 64), TB>>>(p_t10, EMB_, W0 + 1 * EMB_ * HID_, HID_, p_xa, b0, 1);
    k_gemm<<<dim3(N_ / 128, HID_ / 64), TB>>>(p_t20, EMB_, W0 + 2 * EMB_ * HID_, HID_, p_xa, b0, 1);

    // ---- layer 1: 192 -> 192 ----
    k_prop<64><<<dim3(G_, 3), TB, smem64>>>(p_xa, HID_, nullptr, p_t1, 1.f, 0.f);
    k_prop<64><<<dim3(G_, 3), TB, smem64>>>(p_t1, HID_, p_xa, p_t2, 2.f, -1.f);
    k_gemm<<<dim3(N_ / 128, HID_ / 64), TB>>>(p_xa, HID_, W1,                 HID_, p_xb, b1c, 0);
    k_gemm<<<dim3(N_ / 128, HID_ / 64), TB>>>(p_t1, HID_, W1 + 1 * HID_ * HID_, HID_, p_xb, b1c, 1);
    k_gemm<<<dim3(N_ / 128, HID_ / 64), TB>>>(p_t2, HID_, W1 + 2 * HID_ * HID_, HID_, p_xb, b1c, 1);

    // ---- layer 2: 192 -> 128 ----
    k_prop<64><<<dim3(G_, 3), TB, smem64>>>(p_xb, HID_, nullptr, p_t1, 1.f, 0.f);
    k_prop<64><<<dim3(G_, 3), TB, smem64>>>(p_t1, HID_, p_xb, p_t2, 2.f, -1.f);
    k_gemm<<<dim3(N_ / 128, OUTC_ / 64), TB>>>(p_xb, HID_, W2,                  OUTC_, p_xa, b2c, 0);
    k_gemm<<<dim3(N_ / 128, OUTC_ / 64), TB>>>(p_t1, HID_, W2 + 1 * HID_ * OUTC_, OUTC_, p_xa, b2c, 1);
    k_gemm<<<dim3(N_ / 128, OUTC_ / 64), TB>>>(p_t2, HID_, W2 + 2 * HID_ * OUTC_, OUTC_, p_xa, b2c, 1);

    // ---- pool + classifier ----
    k_pool<<<G_, OUTC_>>>(p_xa);
    k_cls<<<G_, MODEL_>>>(demo, cw1, cb1, cw2, cb2, out);
}

// round 4
// speedup vs baseline: 1.1979x; 1.1979x over previous
#include <cuda_runtime.h>
#include <cuda_bf16.h>
#include <cstdint>

// Problem constants
#define G_   64
#define NPG_ 400
#define N_   25600          // G_*NPG_
#define DEG_ 40
#define E_   1024000        // N_*DEG_
#define EMB_ 16
#define HID_ 192
#define OUTC_ 128
#define MODEL_ 64
#define DEMO_ 5

// ---------------- device scratch (no allocations allowed) ----------------
__device__ float g_deg[N_];
__device__ float g_dis[N_];
__device__ float g_norm[E_];
__device__ int   g_counts[N_];
__device__ int   g_rowptr[N_ + 1];
__device__ int   g_cursor[N_];
__device__ int2  g_csr[E_];            // .x = src local, .y = norm bits
__device__ float g_x0 [N_ * EMB_];
__device__ float g_t10[N_ * EMB_];
__device__ float g_t20[N_ * EMB_];
__device__ float g_xa [N_ * HID_];
__device__ float g_xb [N_ * HID_];
__device__ float g_t1 [N_ * HID_];
__device__ float g_t2 [N_ * HID_];
__device__ float g_gfeat[G_ * OUTC_];
// fragment-packed weights: uint4 per (term, n8-tile, k16-step, lane)
// .x/.y = hi bf16x2 pairs (b0,b1), .z/.w = lo bf16x2 pairs
__device__ uint4 g_wp0[3 * (HID_  / 8) * (EMB_ / 16) * 32];   // 2304
__device__ uint4 g_wp1[3 * (HID_  / 8) * (HID_ / 16) * 32];   // 27648
__device__ uint4 g_wp2[3 * (OUTC_ / 8) * (HID_ / 16) * 32];   // 18432

// ---------------- helpers ----------------
__device__ __forceinline__ unsigned short bfbits(__nv_bfloat16 h) {
    __nv_bfloat16_raw r = *reinterpret_cast<__nv_bfloat16_raw*>(&h);
    return r.x;
}

__device__ __forceinline__ void cvt_hilo(float2 f, uint32_t& h, uint32_t& l) {
    __nv_bfloat16 h0 = __float2bfloat16(f.x);
    __nv_bfloat16 h1 = __float2bfloat16(f.y);
    __nv_bfloat16 l0 = __float2bfloat16(f.x - __bfloat162float(h0));
    __nv_bfloat16 l1 = __float2bfloat16(f.y - __bfloat162float(h1));
    h = (uint32_t)bfbits(h0) | ((uint32_t)bfbits(h1) << 16);
    l = (uint32_t)bfbits(l0) | ((uint32_t)bfbits(l1) << 16);
}

__device__ __forceinline__ void mma_bf16(float* c, const uint32_t* a,
                                         uint32_t b0, uint32_t b1) {
    asm volatile(
        "mma.sync.aligned.m16n8k16.row.col.f32.bf16.bf16.f32 "
        "{%0,%1,%2,%3}, {%4,%5,%6,%7}, {%8,%9}, {%0,%1,%2,%3};"
        : "+f"(c[0]), "+f"(c[1]), "+f"(c[2]), "+f"(c[3])
        : "r"(a[0]), "r"(a[1]), "r"(a[2]), "r"(a[3]), "r"(b0), "r"(b1));
}

// ---------------- preprocessing ----------------
__global__ void k_deg(const int* __restrict__ src, const float* __restrict__ ea) {
    int i = blockIdx.x * blockDim.x + threadIdx.x;
    if (i < E_) atomicAdd(&g_deg[src[i]], ea[i]);
}

__global__ void k_dis() {
    int i = blockIdx.x * blockDim.x + threadIdx.x;
    if (i < N_) {
        float d = g_deg[i];
        float r = 0.f;
        if (d > 0.f) {
            r = rsqrtf(d);
            r = r * (1.5f - 0.5f * d * r * r);
        }
        g_dis[i] = r;
    }
}

__global__ void k_norm(const int* __restrict__ src, const int* __restrict__ dst,
                       const float* __restrict__ ea) {
    int i = blockIdx.x * blockDim.x + threadIdx.x;
    if (i < E_) {
        int s = src[i], t = dst[i];
        g_norm[i] = -g_dis[s] * ea[i] * g_dis[t];
        atomicAdd(&g_counts[t], 1);
    }
}

__global__ void k_scan() {
    __shared__ int s[NPG_];
    int g = blockIdx.x, t = threadIdx.x;
    int v = 0;
    if (t < NPG_) { v = g_counts[g * NPG_ + t]; s[t] = v; }
    __syncthreads();
    for (int off = 1; off < NPG_; off <<= 1) {
        int x = 0;
        if (t < NPG_ && t >= off) x = s[t - off];
        __syncthreads();
        if (t < NPG_) s[t] += x;
        __syncthreads();
    }
    if (t < NPG_) {
        int excl = g * (NPG_ * DEG_) + s[t] - v;
        g_rowptr[g * NPG_ + t] = excl;
        g_cursor[g * NPG_ + t] = excl;
    }
    if (g == 0 && t == 0) g_rowptr[N_] = E_;
}

__global__ void k_scatter(const int* __restrict__ src, const int* __restrict__ dst) {
    int i = blockIdx.x * blockDim.x + threadIdx.x;
    if (i < E_) {
        int t = dst[i];
        int p = atomicAdd(&g_cursor[t], 1);
        int sl = src[i] % NPG_;
        g_csr[p] = make_int2(sl, __float_as_int(g_norm[i]));
    }
}

__global__ void k_embed(const int* __restrict__ ids, const float* __restrict__ emb) {
    int i = blockIdx.x * blockDim.x + threadIdx.x;
    if (i < N_ * EMB_) {
        int n = i >> 4, c = i & 15;
        g_x0[i] = emb[ids[n] * EMB_ + c];
    }
}

// weight prep: W[t][k][n] fp32 -> per-lane mma B-fragment uint4 layout
__global__ void k_wprep(const float* __restrict__ W, int KT, int NO,
                        uint4* __restrict__ dst) {
    const int NT = NO / 8, NKS = KT / 16;
    int idx = blockIdx.x * blockDim.x + threadIdx.x;
    int tot = 3 * NT * NKS * 32;
    if (idx >= tot) return;
    int lane = idx & 31;
    int r = idx >> 5;
    int ks = r % NKS; r /= NKS;
    int ntile = r % NT;
    int t = r / NT;
    int n = ntile * 8 + (lane >> 2);
    int q = (lane & 3) * 2;
    int kb = ks * 16;
    const float* Wt = W + (size_t)t * KT * NO;
    float w0 = Wt[(kb + q + 0) * NO + n];
    float w1 = Wt[(kb + q + 1) * NO + n];
    float w2 = Wt[(kb + q + 8) * NO + n];
    float w3 = Wt[(kb + q + 9) * NO + n];
    uint32_t h01, l01, h23, l23;
    cvt_hilo(make_float2(w0, w1), h01, l01);
    cvt_hilo(make_float2(w2, w3), h23, l23);
    uint4 v; v.x = h01; v.y = h23; v.z = l01; v.w = l23;
    dst[idx] = v;
}

// ---------------- propagation ----------------
template <int D>
__global__ void k_prop(const float* __restrict__ h, int dtot,
                       const float* __restrict__ bsrc,
                       float* __restrict__ out,
                       float alpha, float beta) {
    extern __shared__ float hs[];
    const int g  = blockIdx.x;
    const int cb = blockIdx.y * D;
    const int tid = threadIdx.x;

    const float* hb = h + (size_t)g * NPG_ * dtot + cb;
    for (int i = tid; i < NPG_ * D; i += blockDim.x) {
        int n = i / D, c = i % D;
        hs[i] = hb[n * dtot + c];
    }
    __syncthreads();

    constexpr int LPN = D / 2;
    const int sub   = tid % LPN;
    const int n0    = tid / LPN;
    const int nstep = blockDim.x / LPN;
    const int c     = 2 * sub;

    for (int n = n0; n < NPG_; n += nstep) {
        const int node = g * NPG_ + n;
        const int beg = g_rowptr[node];
        const int end = g_rowptr[node + 1];
        float ax = 0.f, ay = 0.f;
        int e = beg;
        for (; e + 2 <= end; e += 2) {
            int2 p0 = g_csr[e];
            int2 p1 = g_csr[e + 1];
            float w0 = __int_as_float(p0.y);
            float w1 = __int_as_float(p1.y);
            float2 h0 = *reinterpret_cast<const float2*>(&hs[p0.x * D + c]);
            float2 h1 = *reinterpret_cast<const float2*>(&hs[p1.x * D + c]);
            ax = fmaf(w0, h0.x, ax);  ay = fmaf(w0, h0.y, ay);
            ax = fmaf(w1, h1.x, ax);  ay = fmaf(w1, h1.y, ay);
        }
        for (; e < end; ++e) {
            int2 p = g_csr[e];
            float w = __int_as_float(p.y);
            float2 hv = *reinterpret_cast<const float2*>(&hs[p.x * D + c]);
            ax = fmaf(w, hv.x, ax);  ay = fmaf(w, hv.y, ay);
        }
        float ox = alpha * ax, oy = alpha * ay;
        if (bsrc != nullptr) {
            const float* bp = bsrc + (size_t)node * dtot + cb + c;
            ox = fmaf(beta, bp[0], ox);
            oy = fmaf(beta, bp[1], oy);
        }
        float* op = out + (size_t)node * dtot + cb + c;
        op[0] = ox;  op[1] = oy;
    }
}

// ---------------- HMMA fused layer GEMM ----------------
// out[128 x NOUT] = bias + sum_t (A_t[128 x KTERM] @ W[t]^T)
// bf16 hi/lo split (hi@hi + hi@lo + lo@hi), fp32 accumulation in registers.
// 8 warps: 4 row-warps x 2 col-warps; warp tile 32 x (NOUT/2). No SMEM, no syncs.
template <int KTERM, int NOUT>
__global__ __launch_bounds__(256, 1)
void k_hgemm(const float* __restrict__ A0, const float* __restrict__ A1,
             const float* __restrict__ A2,
             const uint4* __restrict__ Wp,
             const float* __restrict__ bias, float* __restrict__ out) {
    constexpr int NKS = KTERM / 16;
    constexpr int NT  = NOUT / 8;
    constexpr int NTW = NT / 2;                 // n8-tiles per warp
    const int tid = threadIdx.x;
    const int wid = tid >> 5;
    const int lane = tid & 31;
    const int wm = wid & 3;                     // row warp
    const int wn = wid >> 2;                    // col warp
    const int row0 = blockIdx.x * 128 + wm * 32;
    const int q  = (lane & 3) * 2;
    const int rr = lane >> 2;

    float acc[2][NTW][4];
    #pragma unroll
    for (int a = 0; a < 2; ++a)
        #pragma unroll
        for (int b = 0; b < NTW; ++b)
            #pragma unroll
            for (int c = 0; c < 4; ++c) acc[a][b][c] = 0.f;

    const float* Asrc[3] = {A0, A1, A2};

    #pragma unroll
    for (int t = 0; t < 3; ++t) {
        const float* A = Asrc[t];
        const uint4* W = Wp + (size_t)t * NT * NKS * 32;
        #pragma unroll
        for (int ks = 0; ks < NKS; ++ks) {
            uint32_t ah[2][4], al[2][4];
            #pragma unroll
            for (int mt = 0; mt < 2; ++mt) {
                const float* base = A + (size_t)(row0 + mt * 16 + rr) * KTERM + ks * 16 + q;
                float2 f0 = *reinterpret_cast<const float2*>(base);
                float2 f1 = *reinterpret_cast<const float2*>(base + 8 * KTERM);
                float2 f2 = *reinterpret_cast<const float2*>(base + 8);
                float2 f3 = *reinterpret_cast<const float2*>(base + 8 * KTERM + 8);
                cvt_hilo(f0, ah[mt][0], al[mt][0]);
                cvt_hilo(f1, ah[mt][1], al[mt][1]);
                cvt_hilo(f2, ah[mt][2], al[mt][2]);
                cvt_hilo(f3, ah[mt][3], al[mt][3]);
            }
            #pragma unroll
            for (int nt = 0; nt < NTW; ++nt) {
                const int ntg = wn * NTW + nt;
                const uint4 b = W[((size_t)ntg * NKS + ks) * 32 + lane];
                #pragma unroll
                for (int mt = 0; mt < 2; ++mt) {
                    mma_bf16(acc[mt][nt], ah[mt], b.x, b.y);   // hi @ hi
                    mma_bf16(acc[mt][nt], ah[mt], b.z, b.w);   // hi @ lo
                    mma_bf16(acc[mt][nt], al[mt], b.x, b.y);   // lo @ hi
                }
            }
        }
    }

    // epilogue: bias + store
    #pragma unroll
    for (int nt = 0; nt < NTW; ++nt) {
        const int col = wn * NTW * 8 + nt * 8 + q;
        const float bx = bias[col], by = bias[col + 1];
        #pragma unroll
        for (int mt = 0; mt < 2; ++mt) {
            const int r = row0 + mt * 16 + rr;
            float2 v0 = make_float2(acc[mt][nt][0] + bx, acc[mt][nt][1] + by);
            float2 v1 = make_float2(acc[mt][nt][2] + bx, acc[mt][nt][3] + by);
            *reinterpret_cast<float2*>(out + (size_t)r * NOUT + col) = v0;
            *reinterpret_cast<float2*>(out + (size_t)(r + 8) * NOUT + col) = v1;
        }
    }
}

// ---------------- pooling + classifier ----------------
__global__ void k_pool(const float* __restrict__ x) {
    int g = blockIdx.x, c = threadIdx.x;
    const float* p = x + (size_t)g * NPG_ * OUTC_ + c;
    float s = 0.f;
    for (int n = 0; n < NPG_; ++n) s += p[n * OUTC_];
    g_gfeat[g * OUTC_ + c] = s * (1.0f / NPG_);
}

__global__ void k_cls(const float* __restrict__ demo,
                      const float* __restrict__ w1, const float* __restrict__ b1,
                      const float* __restrict__ w2, const float* __restrict__ b2,
                      float* __restrict__ out) {
    __shared__ float f[OUTC_ + DEMO_];
    __shared__ float h[MODEL_];
    int g = blockIdx.x, m = threadIdx.x;
    f[m] = g_gfeat[g * OUTC_ + m];
    f[64 + m] = g_gfeat[g * OUTC_ + 64 + m];
    if (m < DEMO_) f[OUTC_ + m] = demo[g * DEMO_ + m];
    __syncthreads();
    float acc = b1[m];
    for (int j = 0; j < OUTC_ + DEMO_; ++j)
        acc = fmaf(f[j], w1[j * MODEL_ + m], acc);
    h[m] = fmaxf(acc, 0.f);
    __syncthreads();
    if (m < 2) {
        float a = b2[m];
        for (int k = 0; k < MODEL_; ++k)
            a = fmaf(h[k], w2[k * 2 + m], a);
        out[g * 2 + m] = a;
    }
}

// ---------------- launcher ----------------
extern "C" void kernel_launch(void* const* d_in, const int* in_sizes, int n_in,
                              void* d_out, int out_size) {
    const int*   node_ids = (const int*)  d_in[0];
    const int*   eidx     = (const int*)  d_in[1];
    const float* eattr    = (const float*)d_in[3];
    const float* demo     = (const float*)d_in[4];
    const float* emb      = (const float*)d_in[5];
    const float* W0       = (const float*)d_in[6];
    const float* b0       = (const float*)d_in[7];
    const float* W1       = (const float*)d_in[8];
    const float* b1c      = (const float*)d_in[9];
    const float* W2       = (const float*)d_in[10];
    const float* b2c      = (const float*)d_in[11];
    const float* cw1      = (const float*)d_in[12];
    const float* cb1      = (const float*)d_in[13];
    const float* cw2      = (const float*)d_in[14];
    const float* cb2      = (const float*)d_in[15];
    float* out = (float*)d_out;

    const int* src = eidx;
    const int* dst = eidx + E_;

    float *p_deg, *p_x0, *p_t10, *p_t20, *p_xa, *p_xb, *p_t1, *p_t2;
    int *p_counts;
    uint4 *wp0, *wp1, *wp2;
    cudaGetSymbolAddress((void**)&p_deg,    g_deg);
    cudaGetSymbolAddress((void**)&p_counts, g_counts);
    cudaGetSymbolAddress((void**)&p_x0,  g_x0);
    cudaGetSymbolAddress((void**)&p_t10, g_t10);
    cudaGetSymbolAddress((void**)&p_t20, g_t20);
    cudaGetSymbolAddress((void**)&p_xa,  g_xa);
    cudaGetSymbolAddress((void**)&p_xb,  g_xb);
    cudaGetSymbolAddress((void**)&p_t1,  g_t1);
    cudaGetSymbolAddress((void**)&p_t2,  g_t2);
    cudaGetSymbolAddress((void**)&wp0, g_wp0);
    cudaGetSymbolAddress((void**)&wp1, g_wp1);
    cudaGetSymbolAddress((void**)&wp2, g_wp2);

    cudaFuncSetAttribute(k_prop<64>, cudaFuncAttributeMaxDynamicSharedMemorySize,
                         NPG_ * 64 * (int)sizeof(float));

    const int TB = 256;
    const int EB = E_ / TB;
    const int NB = (N_ + TB - 1) / TB;

    // preprocessing
    cudaMemsetAsync(p_deg, 0, N_ * sizeof(float), 0);
    cudaMemsetAsync(p_counts, 0, N_ * sizeof(int), 0);
    k_deg<<<EB, TB>>>(src, eattr);
    k_dis<<<NB, TB>>>();
    k_norm<<<EB, TB>>>(src, dst, eattr);
    k_scan<<<G_, 512>>>();
    k_scatter<<<EB, TB>>>(src, dst);
    k_embed<<<(N_ * EMB_) / TB, TB>>>(node_ids, emb);

    // weight prep (fragment-packed bf16 hi/lo)
    k_wprep<<<(3 * (HID_ / 8) * (EMB_ / 16) * 32 + TB - 1) / TB, TB>>>(W0, EMB_, HID_, wp0);
    k_wprep<<<(3 * (HID_ / 8) * (HID_ / 16) * 32 + TB - 1) / TB, TB>>>(W1, HID_, HID_, wp1);
    k_wprep<<<(3 * (OUTC_ / 8) * (HID_ / 16) * 32 + TB - 1) / TB, TB>>>(W2, HID_, OUTC_, wp2);

    const size_t smem16 = NPG_ * 16 * sizeof(float);
    const size_t smem64 = NPG_ * 64 * sizeof(float);

    // ---- layer 0: 16 -> 192 ----
    k_prop<16><<<dim3(G_, 1), TB, smem16>>>(p_x0, EMB_, nullptr, p_t10, 1.f, 0.f);
    k_prop<16><<<dim3(G_, 1), TB, smem16>>>(p_t10, EMB_, p_x0, p_t20, 2.f, -1.f);
    k_hgemm<EMB_, HID_><<<N_ / 128, 256>>>(p_x0, p_t10, p_t20, wp0, b0, p_xa);

    // ---- layer 1: 192 -> 192 ----
    k_prop<64><<<dim3(G_, 3), TB, smem64>>>(p_xa, HID_, nullptr, p_t1, 1.f, 0.f);
    k_prop<64><<<dim3(G_, 3), TB, smem64>>>(p_t1, HID_, p_xa, p_t2, 2.f, -1.f);
    k_hgemm<HID_, HID_><<<N_ / 128, 256>>>(p_xa, p_t1, p_t2, wp1, b1c, p_xb);

    // ---- layer 2: 192 -> 128 ----
    k_prop<64><<<dim3(G_, 3), TB, smem64>>>(p_xb, HID_, nullptr, p_t1, 1.f, 0.f);
    k_prop<64><<<dim3(G_, 3), TB, smem64>>>(p_t1, HID_, p_xb, p_t2, 2.f, -1.f);
    k_hgemm<HID_, OUTC_><<<N_ / 128, 256>>>(p_xb, p_t1, p_t2, wp2, b2c, p_xa);

    // ---- pool + classifier ----
    k_pool<<<G_, OUTC_>>>(p_xa);
    k_cls<<<G_, MODEL_>>>(demo, cw1, cb1, cw2, cb2, out);
}

// round 6
// speedup vs baseline: 1.3171x; 1.0995x over previous
#include <cuda_runtime.h>
#include <cuda_bf16.h>
#include <cstdint>

// Problem constants
#define G_   64
#define NPG_ 400
#define N_   25600          // G_*NPG_
#define DEG_ 40
#define E_   1024000        // N_*DEG_
#define EMB_ 16
#define HID_ 192
#define OUTC_ 128
#define MODEL_ 64
#define DEMO_ 5

// ---------------- device scratch (no allocations allowed) ----------------
__device__ int   g_rowptr[N_ + 1];
__device__ int2  g_csr[E_];            // .x = src local, .y = norm bits
__device__ float g_x0 [N_ * EMB_];
__device__ float g_t10[N_ * EMB_];
__device__ float g_t20[N_ * EMB_];
__device__ float g_xa [N_ * HID_];
__device__ float g_xb [N_ * HID_];
__device__ float g_t1 [N_ * HID_];
__device__ float g_t2 [N_ * HID_];
__device__ float g_gfeat[G_ * OUTC_];
// fragment-packed weights: uint4 per (term, n8-tile, k16-step, lane)
// .x/.y = hi bf16x2 pairs, .z/.w = lo bf16x2 pairs
__device__ uint4 g_wp0[3 * (HID_  / 8) * (EMB_ / 16) * 32];
__device__ uint4 g_wp1[3 * (HID_  / 8) * (HID_ / 16) * 32];
__device__ uint4 g_wp2[3 * (OUTC_ / 8) * (HID_ / 16) * 32];

// ---------------- helpers ----------------
__device__ __forceinline__ unsigned short bfbits(__nv_bfloat16 h) {
    __nv_bfloat16_raw r = *reinterpret_cast<__nv_bfloat16_raw*>(&h);
    return r.x;
}

__device__ __forceinline__ void cvt_hilo(float2 f, uint32_t& h, uint32_t& l) {
    __nv_bfloat16 h0 = __float2bfloat16(f.x);
    __nv_bfloat16 h1 = __float2bfloat16(f.y);
    __nv_bfloat16 l0 = __float2bfloat16(f.x - __bfloat162float(h0));
    __nv_bfloat16 l1 = __float2bfloat16(f.y - __bfloat162float(h1));
    h = (uint32_t)bfbits(h0) | ((uint32_t)bfbits(h1) << 16);
    l = (uint32_t)bfbits(l0) | ((uint32_t)bfbits(l1) << 16);
}

__device__ __forceinline__ void mma_bf16(float* c, const uint32_t* a,
                                         uint32_t b0, uint32_t b1) {
    asm volatile(
        "mma.sync.aligned.m16n8k16.row.col.f32.bf16.bf16.f32 "
        "{%0,%1,%2,%3}, {%4,%5,%6,%7}, {%8,%9}, {%0,%1,%2,%3};"
        : "+f"(c[0]), "+f"(c[1]), "+f"(c[2]), "+f"(c[3])
        : "r"(a[0]), "r"(a[1]), "r"(a[2]), "r"(a[3]), "r"(b0), "r"(b1));
}

__device__ __forceinline__ uint32_t smem_u32(const void* p) {
    uint32_t a;
    asm("{ .reg .u64 t; cvta.to.shared.u64 t, %1; cvt.u32.u64 %0, t; }" : "=r"(a) : "l"(p));
    return a;
}

__device__ __forceinline__ void ldsm_x4(uint32_t* r, uint32_t saddr) {
    asm volatile("ldmatrix.sync.aligned.m8n8.x4.shared.b16 {%0,%1,%2,%3}, [%4];"
        : "=r"(r[0]), "=r"(r[1]), "=r"(r[2]), "=r"(r[3]) : "r"(saddr));
}

// ---------------- fused per-graph preprocessing ----------------
// One CTA per graph (edges of graph g are [g*16000, (g+1)*16000)):
// deg histogram -> rsqrt -> counts -> scan -> norm+scatter. SMEM atomics only.
__global__ __launch_bounds__(512)
void k_pre(const int* __restrict__ src, const int* __restrict__ dst,
           const float* __restrict__ ea) {
    __shared__ float sdeg[NPG_];
    __shared__ float sdis[NPG_];
    __shared__ int   scnt[NPG_];
    __shared__ int   sscan[NPG_];
    __shared__ int   scur[NPG_];
    const int g = blockIdx.x, tid = threadIdx.x;
    const int eb = g * (NPG_ * DEG_);
    const int nb = g * NPG_;

    if (tid < NPG_) { sdeg[tid] = 0.f; scnt[tid] = 0; }
    __syncthreads();

    for (int e = tid; e < NPG_ * DEG_; e += 512) {
        int s = src[eb + e] - nb;
        int t = dst[eb + e] - nb;
        atomicAdd(&sdeg[s], ea[eb + e]);
        atomicAdd(&scnt[t], 1);
    }
    __syncthreads();

    if (tid < NPG_) {
        float d = sdeg[tid];
        float r = 0.f;
        if (d > 0.f) {
            r = rsqrtf(d);
            r = r * (1.5f - 0.5f * d * r * r);   // Newton refine
        }
        sdis[tid] = r;
        sscan[tid] = scnt[tid];
    }
    __syncthreads();

    for (int off = 1; off < NPG_; off <<= 1) {
        int x = 0;
        if (tid < NPG_ && tid >= off) x = sscan[tid - off];
        __syncthreads();
        if (tid < NPG_) sscan[tid] += x;
        __syncthreads();
    }
    if (tid < NPG_) {
        int excl = eb + sscan[tid] - scnt[tid];
        g_rowptr[nb + tid] = excl;
        scur[tid] = excl;
    }
    if (g == 0 && tid == 0) g_rowptr[N_] = E_;
    __syncthreads();

    for (int e = tid; e < NPG_ * DEG_; e += 512) {
        int s = src[eb + e] - nb;
        int t = dst[eb + e] - nb;
        float w = -sdis[s] * ea[eb + e] * sdis[t];
        int p = atomicAdd(&scur[t], 1);
        g_csr[p] = make_int2(s, __float_as_int(w));
    }
}

// ---------------- fused embed + both d=16 props (layer 0 inputs) ----------------
__global__ __launch_bounds__(256)
void k_embprop(const int* __restrict__ ids, const float* __restrict__ emb) {
    extern __shared__ float sm[];
    float* x0s = sm;                 // 400*16
    float* t1s = sm + NPG_ * EMB_;   // 400*16
    const int g = blockIdx.x, tid = threadIdx.x;
    const int nb = g * NPG_;

    for (int i = tid; i < NPG_ * EMB_; i += 256) {
        int n = i >> 4, c = i & 15;
        float v = emb[ids[nb + n] * EMB_ + c];
        x0s[i] = v;
        g_x0[(size_t)nb * EMB_ + i] = v;
    }
    __syncthreads();

    const int sub = tid & 7;          // 8 lanes per node (2 ch each)
    const int n0  = tid >> 3;         // 32 nodes in flight
    const int c   = sub * 2;

    // t1 = P x0
    for (int n = n0; n < NPG_; n += 32) {
        int beg = g_rowptr[nb + n], end = g_rowptr[nb + n + 1];
        float ax = 0.f, ay = 0.f;
        for (int e = beg; e < end; ++e) {
            int2 p = g_csr[e];
            float w = __int_as_float(p.y);
            ax = fmaf(w, x0s[p.x * EMB_ + c], ax);
            ay = fmaf(w, x0s[p.x * EMB_ + c + 1], ay);
        }
        t1s[n * EMB_ + c] = ax;  t1s[n * EMB_ + c + 1] = ay;
        g_t10[(size_t)(nb + n) * EMB_ + c] = ax;
        g_t10[(size_t)(nb + n) * EMB_ + c + 1] = ay;
    }
    __syncthreads();

    // t2 = 2 P t1 - x0
    for (int n = n0; n < NPG_; n += 32) {
        int beg = g_rowptr[nb + n], end = g_rowptr[nb + n + 1];
        float ax = 0.f, ay = 0.f;
        for (int e = beg; e < end; ++e) {
            int2 p = g_csr[e];
            float w = __int_as_float(p.y);
            ax = fmaf(w, t1s[p.x * EMB_ + c], ax);
            ay = fmaf(w, t1s[p.x * EMB_ + c + 1], ay);
        }
        g_t20[(size_t)(nb + n) * EMB_ + c]     = 2.f * ax - x0s[n * EMB_ + c];
        g_t20[(size_t)(nb + n) * EMB_ + c + 1] = 2.f * ay - x0s[n * EMB_ + c + 1];
    }
}

// weight prep: W[t][k][n] fp32 -> per-lane mma B-fragment uint4 layout
__global__ void k_wprep(const float* __restrict__ W, int KT, int NO,
                        uint4* __restrict__ dst) {
    const int NT = NO / 8, NKS = KT / 16;
    int idx = blockIdx.x * blockDim.x + threadIdx.x;
    int tot = 3 * NT * NKS * 32;
    if (idx >= tot) return;
    int lane = idx & 31;
    int r = idx >> 5;
    int ks = r % NKS; r /= NKS;
    int ntile = r % NT;
    int t = r / NT;
    int n = ntile * 8 + (lane >> 2);
    int q = (lane & 3) * 2;
    int kb = ks * 16;
    const float* Wt = W + (size_t)t * KT * NO;
    float w0 = Wt[(kb + q + 0) * NO + n];
    float w1 = Wt[(kb + q + 1) * NO + n];
    float w2 = Wt[(kb + q + 8) * NO + n];
    float w3 = Wt[(kb + q + 9) * NO + n];
    uint32_t h01, l01, h23, l23;
    cvt_hilo(make_float2(w0, w1), h01, l01);
    cvt_hilo(make_float2(w2, w3), h23, l23);
    uint4 v; v.x = h01; v.y = h23; v.z = l01; v.w = l23;
    dst[idx] = v;
}

// ---------------- d=64-chunk propagation (layers 1,2) ----------------
template <int D>
__global__ void k_prop(const float* __restrict__ h, int dtot,
                       const float* __restrict__ bsrc,
                       float* __restrict__ out,
                       float alpha, float beta) {
    extern __shared__ float hs[];
    const int g  = blockIdx.x;
    const int cb = blockIdx.y * D;
    const int tid = threadIdx.x;

    const float* hb = h + (size_t)g * NPG_ * dtot + cb;
    for (int i = tid; i < NPG_ * D; i += blockDim.x) {
        int n = i / D, c = i % D;
        hs[i] = hb[n * dtot + c];
    }
    __syncthreads();

    constexpr int LPN = D / 2;
    const int sub   = tid % LPN;
    const int n0    = tid / LPN;
    const int nstep = blockDim.x / LPN;
    const int c     = 2 * sub;

    for (int n = n0; n < NPG_; n += nstep) {
        const int node = g * NPG_ + n;
        const int beg = g_rowptr[node];
        const int end = g_rowptr[node + 1];
        float ax = 0.f, ay = 0.f;
        int e = beg;
        for (; e + 2 <= end; e += 2) {
            int2 p0 = g_csr[e];
            int2 p1 = g_csr[e + 1];
            float w0 = __int_as_float(p0.y);
            float w1 = __int_as_float(p1.y);
            float2 h0 = *reinterpret_cast<const float2*>(&hs[p0.x * D + c]);
            float2 h1 = *reinterpret_cast<const float2*>(&hs[p1.x * D + c]);
            ax = fmaf(w0, h0.x, ax);  ay = fmaf(w0, h0.y, ay);
            ax = fmaf(w1, h1.x, ax);  ay = fmaf(w1, h1.y, ay);
        }
        for (; e < end; ++e) {
            int2 p = g_csr[e];
            float w = __int_as_float(p.y);
            float2 hv = *reinterpret_cast<const float2*>(&hs[p.x * D + c]);
            ax = fmaf(w, hv.x, ax);  ay = fmaf(w, hv.y, ay);
        }
        float ox = alpha * ax, oy = alpha * ay;
        if (bsrc != nullptr) {
            const float* bp = bsrc + (size_t)node * dtot + cb + c;
            ox = fmaf(beta, bp[0], ox);
            oy = fmaf(beta, bp[1], oy);
        }
        float* op = out + (size_t)node * dtot + cb + c;
        op[0] = ox;  op[1] = oy;
    }
}

// ---------------- HMMA fused layer GEMM v2 ----------------
// 64-row CTA tile, A staged in SMEM as hi/lo bf16 (converted once per CTA),
// fragments via ldmatrix; B via pre-packed uint4 LDG.128. 2 CTAs/SM.
// 8 warps = 2 row-warps x 4 col-warps.
template <int KTERM, int NOUT>
__global__ __launch_bounds__(256, 2)
void k_hgemm(const float* __restrict__ A0, const float* __restrict__ A1,
             const float* __restrict__ A2,
             const uint4* __restrict__ Wp,
             const float* __restrict__ bias, float* __restrict__ out) {
    constexpr int KC    = (KTERM >= 64) ? 64 : KTERM;
    constexpr int NCH   = KTERM / KC;
    constexpr int RS    = KC + 8;          // bf16 row stride (conflict-free ldmatrix)
    constexpr int NKS_G = KTERM / 16;
    constexpr int NT    = NOUT / 8;
    constexpr int NTW   = NT / 4;          // n8-tiles per col-warp
    __shared__ __nv_bfloat16 Ah[64 * RS];
    __shared__ __nv_bfloat16 Al[64 * RS];

    const int tid = threadIdx.x;
    const int wid = tid >> 5;
    const int lane = tid & 31;
    const int wm = wid & 1;                // row warp (32 rows each)
    const int wn = wid >> 1;               // col warp
    const int row0 = blockIdx.x * 64;
    const int lrow = lane & 15;
    const int lseg = lane >> 4;

    float acc[2][NTW][4];
    #pragma unroll
    for (int a = 0; a < 2; ++a)
        #pragma unroll
        for (int b = 0; b < NTW; ++b)
            #pragma unroll
            for (int c = 0; c < 4; ++c) acc[a][b][c] = 0.f;

    const uint32_t ah_base = smem_u32(Ah);
    const uint32_t al_base = smem_u32(Al);
    const float* Asrc[3] = {A0, A1, A2};

    #pragma unroll
    for (int t = 0; t < 3; ++t) {
        const float* A = Asrc[t] + (size_t)row0 * KTERM;
        const uint4* W = Wp + (size_t)t * NT * NKS_G * 32;
        #pragma unroll
        for (int ch = 0; ch < NCH; ++ch) {
            const int kc0 = ch * KC;
            // ---- stage A chunk: fp32 -> hi/lo bf16 in SMEM ----
            constexpr int ITER = (64 * KC / 4) / 256;
            #pragma unroll
            for (int it = 0; it < ITER; ++it) {
                const int idx = tid + it * 256;
                const int r = idx / (KC / 4);
                const int cq = (idx % (KC / 4)) * 4;
                const float4 v = *reinterpret_cast<const float4*>(
                    A + (size_t)r * KTERM + kc0 + cq);
                uint32_t h0, l0, h1, l1;
                cvt_hilo(make_float2(v.x, v.y), h0, l0);
                cvt_hilo(make_float2(v.z, v.w), h1, l1);
                uint2 hp, lp;
                hp.x = h0; hp.y = h1;
                lp.x = l0; lp.y = l1;
                *reinterpret_cast<uint2*>(&Ah[r * RS + cq]) = hp;
                *reinterpret_cast<uint2*>(&Al[r * RS + cq]) = lp;
            }
            __syncthreads();

            #pragma unroll
            for (int ks = 0; ks < KC / 16; ++ks) {
                uint32_t ah[2][4], al[2][4];
                #pragma unroll
                for (int mt = 0; mt < 2; ++mt) {
                    const int row = wm * 32 + mt * 16 + lrow;
                    const uint32_t off = (uint32_t)(row * RS + ks * 16) * 2 + lseg * 16;
                    ldsm_x4(ah[mt], ah_base + off);
                    ldsm_x4(al[mt], al_base + off);
                }
                const int ksg = kc0 / 16 + ks;
                #pragma unroll
                for (int nt = 0; nt < NTW; ++nt) {
                    const int ntg = wn * NTW + nt;
                    const uint4 b = W[((size_t)ntg * NKS_G + ksg) * 32 + lane];
                    #pragma unroll
                    for (int mt = 0; mt < 2; ++mt) {
                        mma_bf16(acc[mt][nt], ah[mt], b.x, b.y);   // hi @ hi
                        mma_bf16(acc[mt][nt], ah[mt], b.z, b.w);   // hi @ lo
                        mma_bf16(acc[mt][nt], al[mt], b.x, b.y);   // lo @ hi
                    }
                }
            }
            __syncthreads();
        }
    }

    // epilogue: bias + store
    const int q  = (lane & 3) * 2;
    const int rr = lane >> 2;
    #pragma unroll
    for (int nt = 0; nt < NTW; ++nt) {
        const int col = wn * NTW * 8 + nt * 8 + q;
        const float bx = bias[col], by = bias[col + 1];
        #pragma unroll
        for (int mt = 0; mt < 2; ++mt) {
            const int r = row0 + wm * 32 + mt * 16 + rr;
            float2 v0 = make_float2(acc[mt][nt][0] + bx, acc[mt][nt][1] + by);
            float2 v1 = make_float2(acc[mt][nt][2] + bx, acc[mt][nt][3] + by);
            *reinterpret_cast<float2*>(out + (size_t)r * NOUT + col) = v0;
            *reinterpret_cast<float2*>(out + (size_t)(r + 8) * NOUT + col) = v1;
        }
    }
}

// ---------------- pooling + classifier ----------------
__global__ void k_pool(const float* __restrict__ x) {
    int g = blockIdx.x, c = threadIdx.x;
    const float* p = x + (size_t)g * NPG_ * OUTC_ + c;
    float s = 0.f;
    for (int n = 0; n < NPG_; ++n) s += p[n * OUTC_];
    g_gfeat[g * OUTC_ + c] = s * (1.0f / NPG_);
}

__global__ void k_cls(const float* __restrict__ demo,
                      const float* __restrict__ w1, const float* __restrict__ b1,
                      const float* __restrict__ w2, const float* __restrict__ b2,
                      float* __restrict__ out) {
    __shared__ float f[OUTC_ + DEMO_];
    __shared__ float h[MODEL_];
    int g = blockIdx.x, m = threadIdx.x;
    f[m] = g_gfeat[g * OUTC_ + m];
    f[64 + m] = g_gfeat[g * OUTC_ + 64 + m];
    if (m < DEMO_) f[OUTC_ + m] = demo[g * DEMO_ + m];
    __syncthreads();
    float acc = b1[m];
    for (int j = 0; j < OUTC_ + DEMO_; ++j)
        acc = fmaf(f[j], w1[j * MODEL_ + m], acc);
    h[m] = fmaxf(acc, 0.f);
    __syncthreads();
    if (m < 2) {
        float a = b2[m];
        for (int k = 0; k < MODEL_; ++k)
            a = fmaf(h[k], w2[k * 2 + m], a);
        out[g * 2 + m] = a;
    }
}

// ---------------- launcher ----------------
extern "C" void kernel_launch(void* const* d_in, const int* in_sizes, int n_in,
                              void* d_out, int out_size) {
    const int*   node_ids = (const int*)  d_in[0];
    const int*   eidx     = (const int*)  d_in[1];
    const float* eattr    = (const float*)d_in[3];
    const float* demo     = (const float*)d_in[4];
    const float* emb      = (const float*)d_in[5];
    const float* W0       = (const float*)d_in[6];
    const float* b0       = (const float*)d_in[7];
    const float* W1       = (const float*)d_in[8];
    const float* b1c      = (const float*)d_in[9];
    const float* W2       = (const float*)d_in[10];
    const float* b2c      = (const float*)d_in[11];
    const float* cw1      = (const float*)d_in[12];
    const float* cb1      = (const float*)d_in[13];
    const float* cw2      = (const float*)d_in[14];
    const float* cb2      = (const float*)d_in[15];
    float* out = (float*)d_out;

    const int* src = eidx;
    const int* dst = eidx + E_;

    float *p_x0, *p_t10, *p_t20, *p_xa, *p_xb, *p_t1, *p_t2;
    uint4 *wp0, *wp1, *wp2;
    cudaGetSymbolAddress((void**)&p_x0,  g_x0);
    cudaGetSymbolAddress((void**)&p_t10, g_t10);
    cudaGetSymbolAddress((void**)&p_t20, g_t20);
    cudaGetSymbolAddress((void**)&p_xa,  g_xa);
    cudaGetSymbolAddress((void**)&p_xb,  g_xb);
    cudaGetSymbolAddress((void**)&p_t1,  g_t1);
    cudaGetSymbolAddress((void**)&p_t2,  g_t2);
    cudaGetSymbolAddress((void**)&wp0, g_wp0);
    cudaGetSymbolAddress((void**)&wp1, g_wp1);
    cudaGetSymbolAddress((void**)&wp2, g_wp2);

    cudaFuncSetAttribute(k_prop<64>, cudaFuncAttributeMaxDynamicSharedMemorySize,
                         NPG_ * 64 * (int)sizeof(float));
    cudaFuncSetAttribute(k_embprop, cudaFuncAttributeMaxDynamicSharedMemorySize,
                         2 * NPG_ * EMB_ * (int)sizeof(float));

    const int TB = 256;

    // fused preprocessing + weight prep
    k_pre<<<G_, 512>>>(src, dst, eattr);
    k_wprep<<<(3 * (HID_ / 8) * (EMB_ / 16) * 32 + TB - 1) / TB, TB>>>(W0, EMB_, HID_, wp0);
    k_wprep<<<(3 * (HID_ / 8) * (HID_ / 16) * 32 + TB - 1) / TB, TB>>>(W1, HID_, HID_, wp1);
    k_wprep<<<(3 * (OUTC_ / 8) * (HID_ / 16) * 32 + TB - 1) / TB, TB>>>(W2, HID_, OUTC_, wp2);

    const size_t smemEP = 2 * NPG_ * EMB_ * sizeof(float);
    const size_t smem64 = NPG_ * 64 * sizeof(float);

    // ---- layer 0: 16 -> 192 (embed + both props fused) ----
    k_embprop<<<G_, TB, smemEP>>>(node_ids, emb);
    k_hgemm<EMB_, HID_><<<N_ / 64, 256>>>(p_x0, p_t10, p_t20, wp0, b0, p_xa);

    // ---- layer 1: 192 -> 192 ----
    k_prop<64><<<dim3(G_, 3), TB, smem64>>>(p_xa, HID_, nullptr, p_t1, 1.f, 0.f);
    k_prop<64><<<dim3(G_, 3), TB, smem64>>>(p_t1, HID_, p_xa, p_t2, 2.f, -1.f);
    k_hgemm<HID_, HID_><<<N_ / 64, 256>>>(p_xa, p_t1, p_t2, wp1, b1c, p_xb);

    // ---- layer 2: 192 -> 128 ----
    k_prop<64><<<dim3(G_, 3), TB, smem64>>>(p_xb, HID_, nullptr, p_t1, 1.f, 0.f);
    k_prop<64><<<dim3(G_, 3), TB, smem64>>>(p_t1, HID_, p_xb, p_t2, 2.f, -1.f);
    k_hgemm<HID_, OUTC_><<<N_ / 64, 256>>>(p_xb, p_t1, p_t2, wp2, b2c, p_xa);

    // ---- pool + classifier ----
    k_pool<<<G_, OUTC_>>>(p_xa);
    k_cls<<<G_, MODEL_>>>(demo, cw1, cb1, cw2, cb2, out);
}

// round 7
// speedup vs baseline: 1.6075x; 1.2204x over previous
#include <cuda_runtime.h>
#include <cuda_bf16.h>
#include <cstdint>

// Problem constants
#define G_   64
#define NPG_ 400
#define N_   25600          // G_*NPG_
#define DEG_ 40
#define E_   1024000        // N_*DEG_
#define EMB_ 16
#define HID_ 192
#define OUTC_ 128
#define MODEL_ 64
#define DEMO_ 5

// ---------------- device scratch (no allocations allowed) ----------------
__device__ int   g_rowptr[N_ + 1];
__device__ int2  g_csr[E_];            // .x = src local, .y = norm bits
// split bf16 planes (hi/lo) for all intermediates
__device__ __align__(16) __nv_bfloat16 g_x0h [N_ * EMB_];
__device__ __align__(16) __nv_bfloat16 g_x0l [N_ * EMB_];
__device__ __align__(16) __nv_bfloat16 g_t10h[N_ * EMB_];
__device__ __align__(16) __nv_bfloat16 g_t10l[N_ * EMB_];
__device__ __align__(16) __nv_bfloat16 g_t20h[N_ * EMB_];
__device__ __align__(16) __nv_bfloat16 g_t20l[N_ * EMB_];
__device__ __align__(16) __nv_bfloat16 g_xah [N_ * HID_];
__device__ __align__(16) __nv_bfloat16 g_xal [N_ * HID_];
__device__ __align__(16) __nv_bfloat16 g_xbh [N_ * HID_];
__device__ __align__(16) __nv_bfloat16 g_xbl [N_ * HID_];
__device__ __align__(16) __nv_bfloat16 g_t1h [N_ * HID_];
__device__ __align__(16) __nv_bfloat16 g_t1l [N_ * HID_];
__device__ __align__(16) __nv_bfloat16 g_t2h [N_ * HID_];
__device__ __align__(16) __nv_bfloat16 g_t2l [N_ * HID_];
__device__ float g_xc[N_ * OUTC_];     // final layer output (fp32)
__device__ float g_gfeat[G_ * OUTC_];
// fragment-packed weights: uint4 per (term, n8-tile, k16-step, lane)
__device__ uint4 g_wp0[3 * (HID_  / 8) * (EMB_ / 16) * 32];   // 2304
__device__ uint4 g_wp1[3 * (HID_  / 8) * (HID_ / 16) * 32];   // 27648
__device__ uint4 g_wp2[3 * (OUTC_ / 8) * (HID_ / 16) * 32];   // 18432

// ---------------- helpers ----------------
__device__ __forceinline__ unsigned short bfbits(__nv_bfloat16 h) {
    __nv_bfloat16_raw r = *reinterpret_cast<__nv_bfloat16_raw*>(&h);
    return r.x;
}

__device__ __forceinline__ void cvt_hilo(float2 f, uint32_t& h, uint32_t& l) {
    __nv_bfloat16 h0 = __float2bfloat16(f.x);
    __nv_bfloat16 h1 = __float2bfloat16(f.y);
    __nv_bfloat16 l0 = __float2bfloat16(f.x - __bfloat162float(h0));
    __nv_bfloat16 l1 = __float2bfloat16(f.y - __bfloat162float(h1));
    h = (uint32_t)bfbits(h0) | ((uint32_t)bfbits(h1) << 16);
    l = (uint32_t)bfbits(l0) | ((uint32_t)bfbits(l1) << 16);
}

__device__ __forceinline__ float2 unsplit(uint32_t h, uint32_t l) {
    float2 a = __bfloat1622float2(*reinterpret_cast<__nv_bfloat162*>(&h));
    float2 b = __bfloat1622float2(*reinterpret_cast<__nv_bfloat162*>(&l));
    return make_float2(a.x + b.x, a.y + b.y);
}

__device__ __forceinline__ void mma_bf16(float* c, const uint32_t* a,
                                         uint32_t b0, uint32_t b1) {
    asm volatile(
        "mma.sync.aligned.m16n8k16.row.col.f32.bf16.bf16.f32 "
        "{%0,%1,%2,%3}, {%4,%5,%6,%7}, {%8,%9}, {%0,%1,%2,%3};"
        : "+f"(c[0]), "+f"(c[1]), "+f"(c[2]), "+f"(c[3])
        : "r"(a[0]), "r"(a[1]), "r"(a[2]), "r"(a[3]), "r"(b0), "r"(b1));
}

__device__ __forceinline__ uint32_t smem_u32(const void* p) {
    uint32_t a;
    asm("{ .reg .u64 t; cvta.to.shared.u64 t, %1; cvt.u32.u64 %0, t; }" : "=r"(a) : "l"(p));
    return a;
}

__device__ __forceinline__ void ldsm_x4(uint32_t* r, uint32_t saddr) {
    asm volatile("ldmatrix.sync.aligned.m8n8.x4.shared.b16 {%0,%1,%2,%3}, [%4];"
        : "=r"(r[0]), "=r"(r[1]), "=r"(r[2]), "=r"(r[3]) : "r"(saddr));
}

#define CP_ASYNC16(smem, gptr) \
    asm volatile("cp.async.ca.shared.global [%0], [%1], 16;" \
        :: "r"(smem), "l"(gptr) : "memory")
#define CP_COMMIT() asm volatile("cp.async.commit_group;" ::: "memory")
#define CP_WAIT0()  asm volatile("cp.async.wait_group 0;" ::: "memory")

// ---------------- fused per-graph preprocessing ----------------
__global__ __launch_bounds__(512)
void k_pre(const int* __restrict__ src, const int* __restrict__ dst,
           const float* __restrict__ ea) {
    __shared__ float sdeg[NPG_];
    __shared__ float sdis[NPG_];
    __shared__ int   scnt[NPG_];
    __shared__ int   sscan[NPG_];
    __shared__ int   scur[NPG_];
    const int g = blockIdx.x, tid = threadIdx.x;
    const int eb = g * (NPG_ * DEG_);
    const int nb = g * NPG_;

    if (tid < NPG_) { sdeg[tid] = 0.f; scnt[tid] = 0; }
    __syncthreads();

    for (int e = tid; e < NPG_ * DEG_; e += 512) {
        int s = src[eb + e] - nb;
        int t = dst[eb + e] - nb;
        atomicAdd(&sdeg[s], ea[eb + e]);
        atomicAdd(&scnt[t], 1);
    }
    __syncthreads();

    if (tid < NPG_) {
        float d = sdeg[tid];
        float r = 0.f;
        if (d > 0.f) {
            r = rsqrtf(d);
            r = r * (1.5f - 0.5f * d * r * r);
        }
        sdis[tid] = r;
        sscan[tid] = scnt[tid];
    }
    __syncthreads();

    for (int off = 1; off < NPG_; off <<= 1) {
        int x = 0;
        if (tid < NPG_ && tid >= off) x = sscan[tid - off];
        __syncthreads();
        if (tid < NPG_) sscan[tid] += x;
        __syncthreads();
    }
    if (tid < NPG_) {
        int excl = eb + sscan[tid] - scnt[tid];
        g_rowptr[nb + tid] = excl;
        scur[tid] = excl;
    }
    if (g == 0 && tid == 0) g_rowptr[N_] = E_;
    __syncthreads();

    for (int e = tid; e < NPG_ * DEG_; e += 512) {
        int s = src[eb + e] - nb;
        int t = dst[eb + e] - nb;
        float w = -sdis[s] * ea[eb + e] * sdis[t];
        int p = atomicAdd(&scur[t], 1);
        g_csr[p] = make_int2(s, __float_as_int(w));
    }
}

// ---------------- fused weight prep (all three layers) ----------------
__device__ __forceinline__ void wprep_one(const float* W, int KT, int NO, int idx,
                                          uint4* dst) {
    const int NT = NO / 8, NKS = KT / 16;
    int lane = idx & 31;
    int r = idx >> 5;
    int ks = r % NKS; r /= NKS;
    int ntile = r % NT;
    int t = r / NT;
    int n = ntile * 8 + (lane >> 2);
    int q = (lane & 3) * 2;
    int kb = ks * 16;
    const float* Wt = W + (size_t)t * KT * NO;
    float w0 = Wt[(kb + q + 0) * NO + n];
    float w1 = Wt[(kb + q + 1) * NO + n];
    float w2 = Wt[(kb + q + 8) * NO + n];
    float w3 = Wt[(kb + q + 9) * NO + n];
    uint32_t h01, l01, h23, l23;
    cvt_hilo(make_float2(w0, w1), h01, l01);
    cvt_hilo(make_float2(w2, w3), h23, l23);
    uint4 v; v.x = h01; v.y = h23; v.z = l01; v.w = l23;
    dst[idx] = v;
}

__global__ void k_wprep_all(const float* __restrict__ W0, const float* __restrict__ W1,
                            const float* __restrict__ W2) {
    const int T0 = 3 * (HID_ / 8) * (EMB_ / 16) * 32;    // 2304
    const int T1 = 3 * (HID_ / 8) * (HID_ / 16) * 32;    // 27648
    const int T2 = 3 * (OUTC_ / 8) * (HID_ / 16) * 32;   // 18432
    int idx = blockIdx.x * blockDim.x + threadIdx.x;
    if (idx < T0)                wprep_one(W0, EMB_, HID_,  idx,            g_wp0);
    else if (idx < T0 + T1)      wprep_one(W1, HID_, HID_,  idx - T0,       g_wp1);
    else if (idx < T0 + T1 + T2) wprep_one(W2, HID_, OUTC_, idx - T0 - T1,  g_wp2);
}

// ---------------- fused embed + both d=16 props, split-plane outputs ----------------
__global__ __launch_bounds__(256)
void k_embprop(const int* __restrict__ ids, const float* __restrict__ emb) {
    extern __shared__ float sm[];
    float* x0s = sm;                 // 400*16
    float* t1s = sm + NPG_ * EMB_;   // 400*16
    const int g = blockIdx.x, tid = threadIdx.x;
    const int nb = g * NPG_;

    for (int i = tid; i < NPG_ * EMB_; i += 256) {
        int n = i >> 4, c = i & 15;
        x0s[i] = emb[ids[nb + n] * EMB_ + c];
    }
    __syncthreads();

    // write x0 split planes
    for (int i2 = tid; i2 < NPG_ * (EMB_ / 2); i2 += 256) {
        int n = i2 >> 3, cp = (i2 & 7) * 2;
        uint32_t h, l;
        cvt_hilo(make_float2(x0s[n * EMB_ + cp], x0s[n * EMB_ + cp + 1]), h, l);
        *reinterpret_cast<uint32_t*>(&g_x0h[(size_t)(nb + n) * EMB_ + cp]) = h;
        *reinterpret_cast<uint32_t*>(&g_x0l[(size_t)(nb + n) * EMB_ + cp]) = l;
    }

    const int sub = tid & 7;          // 8 lanes per node (2 ch each)
    const int n0  = tid >> 3;         // 32 nodes in flight
    const int c   = sub * 2;

    // t1 = P x0
    for (int n = n0; n < NPG_; n += 32) {
        int beg = g_rowptr[nb + n], end = g_rowptr[nb + n + 1];
        float ax = 0.f, ay = 0.f;
        for (int e = beg; e < end; ++e) {
            int2 p = g_csr[e];
            float w = __int_as_float(p.y);
            ax = fmaf(w, x0s[p.x * EMB_ + c], ax);
            ay = fmaf(w, x0s[p.x * EMB_ + c + 1], ay);
        }
        t1s[n * EMB_ + c] = ax;  t1s[n * EMB_ + c + 1] = ay;
        uint32_t h, l;
        cvt_hilo(make_float2(ax, ay), h, l);
        *reinterpret_cast<uint32_t*>(&g_t10h[(size_t)(nb + n) * EMB_ + c]) = h;
        *reinterpret_cast<uint32_t*>(&g_t10l[(size_t)(nb + n) * EMB_ + c]) = l;
    }
    __syncthreads();

    // t2 = 2 P t1 - x0
    for (int n = n0; n < NPG_; n += 32) {
        int beg = g_rowptr[nb + n], end = g_rowptr[nb + n + 1];
        float ax = 0.f, ay = 0.f;
        for (int e = beg; e < end; ++e) {
            int2 p = g_csr[e];
            float w = __int_as_float(p.y);
            ax = fmaf(w, t1s[p.x * EMB_ + c], ax);
            ay = fmaf(w, t1s[p.x * EMB_ + c + 1], ay);
        }
        float ox = 2.f * ax - x0s[n * EMB_ + c];
        float oy = 2.f * ay - x0s[n * EMB_ + c + 1];
        uint32_t h, l;
        cvt_hilo(make_float2(ox, oy), h, l);
        *reinterpret_cast<uint32_t*>(&g_t20h[(size_t)(nb + n) * EMB_ + c]) = h;
        *reinterpret_cast<uint32_t*>(&g_t20l[(size_t)(nb + n) * EMB_ + c]) = l;
    }
}

// ---------------- fused prop pair (t1 and t2) on 32-channel chunks ----------------
// h from split planes; t1 kept in SMEM; outputs written as split planes.
__global__ __launch_bounds__(256, 2)
void k_prop2(const __nv_bfloat16* __restrict__ hH, const __nv_bfloat16* __restrict__ hL,
             __nv_bfloat16* __restrict__ t1H, __nv_bfloat16* __restrict__ t1L,
             __nv_bfloat16* __restrict__ t2H, __nv_bfloat16* __restrict__ t2L) {
    extern __shared__ float sm[];
    float* hs  = sm;                 // 400*32
    float* t1s = sm + NPG_ * 32;     // 400*32
    const int g  = blockIdx.x;
    const int cb = blockIdx.y * 32;
    const int tid = threadIdx.x;
    const int nb = g * NPG_;

    // stage h chunk (hi+lo -> fp32)
    for (int i = tid; i < NPG_ * 4; i += 256) {    // 8 values per i
        int n = i >> 2, c = (i & 3) * 8;
        const uint4 hv = *reinterpret_cast<const uint4*>(hH + (size_t)(nb + n) * HID_ + cb + c);
        const uint4 lv = *reinterpret_cast<const uint4*>(hL + (size_t)(nb + n) * HID_ + cb + c);
        const uint32_t* hw = reinterpret_cast<const uint32_t*>(&hv);
        const uint32_t* lw = reinterpret_cast<const uint32_t*>(&lv);
        #pragma unroll
        for (int j = 0; j < 4; ++j) {
            float2 f = unsplit(hw[j], lw[j]);
            hs[n * 32 + c + 2 * j]     = f.x;
            hs[n * 32 + c + 2 * j + 1] = f.y;
        }
    }
    __syncthreads();

    const int sub = tid & 15;         // 16 lanes per node
    const int grp = tid >> 4;         // 16 node groups
    const int c   = sub * 2;

    // t1 = P h
    for (int n = grp; n < NPG_; n += 16) {
        const int beg = g_rowptr[nb + n];
        const int end = g_rowptr[nb + n + 1];
        float ax = 0.f, ay = 0.f;
        int e = beg;
        for (; e + 2 <= end; e += 2) {
            int2 p0 = g_csr[e];
            int2 p1 = g_csr[e + 1];
            float w0 = __int_as_float(p0.y);
            float w1 = __int_as_float(p1.y);
            float2 h0 = *reinterpret_cast<const float2*>(&hs[p0.x * 32 + c]);
            float2 h1 = *reinterpret_cast<const float2*>(&hs[p1.x * 32 + c]);
            ax = fmaf(w0, h0.x, ax);  ay = fmaf(w0, h0.y, ay);
            ax = fmaf(w1, h1.x, ax);  ay = fmaf(w1, h1.y, ay);
        }
        for (; e < end; ++e) {
            int2 p = g_csr[e];
            float w = __int_as_float(p.y);
            float2 hv = *reinterpret_cast<const float2*>(&hs[p.x * 32 + c]);
            ax = fmaf(w, hv.x, ax);  ay = fmaf(w, hv.y, ay);
        }
        t1s[n * 32 + c] = ax;  t1s[n * 32 + c + 1] = ay;
        uint32_t h, l;
        cvt_hilo(make_float2(ax, ay), h, l);
        *reinterpret_cast<uint32_t*>(t1H + (size_t)(nb + n) * HID_ + cb + c) = h;
        *reinterpret_cast<uint32_t*>(t1L + (size_t)(nb + n) * HID_ + cb + c) = l;
    }
    __syncthreads();

    // t2 = 2 P t1 - h
    for (int n = grp; n < NPG_; n += 16) {
        const int beg = g_rowptr[nb + n];
        const int end = g_rowptr[nb + n + 1];
        float ax = 0.f, ay = 0.f;
        int e = beg;
        for (; e + 2 <= end; e += 2) {
            int2 p0 = g_csr[e];
            int2 p1 = g_csr[e + 1];
            float w0 = __int_as_float(p0.y);
            float w1 = __int_as_float(p1.y);
            float2 h0 = *reinterpret_cast<const float2*>(&t1s[p0.x * 32 + c]);
            float2 h1 = *reinterpret_cast<const float2*>(&t1s[p1.x * 32 + c]);
            ax = fmaf(w0, h0.x, ax);  ay = fmaf(w0, h0.y, ay);
            ax = fmaf(w1, h1.x, ax);  ay = fmaf(w1, h1.y, ay);
        }
        for (; e < end; ++e) {
            int2 p = g_csr[e];
            float w = __int_as_float(p.y);
            float2 hv = *reinterpret_cast<const float2*>(&t1s[p.x * 32 + c]);
            ax = fmaf(w, hv.x, ax);  ay = fmaf(w, hv.y, ay);
        }
        float ox = 2.f * ax - hs[n * 32 + c];
        float oy = 2.f * ay - hs[n * 32 + c + 1];
        uint32_t h, l;
        cvt_hilo(make_float2(ox, oy), h, l);
        *reinterpret_cast<uint32_t*>(t2H + (size_t)(nb + n) * HID_ + cb + c) = h;
        *reinterpret_cast<uint32_t*>(t2L + (size_t)(nb + n) * HID_ + cb + c) = l;
    }
}

// ---------------- HMMA fused layer GEMM v3 ----------------
// Inputs as split bf16 planes (no conversion); cp.async double-buffered staging;
// 64-row CTA tile; 8 warps = 2 row-warps x 4 col-warps; 2 CTAs/SM.
template <int KTERM, int NOUT, bool SPLIT_OUT>
__global__ __launch_bounds__(256, 2)
void k_hgemm(const __nv_bfloat16* __restrict__ A0h, const __nv_bfloat16* __restrict__ A0l,
             const __nv_bfloat16* __restrict__ A1h, const __nv_bfloat16* __restrict__ A1l,
             const __nv_bfloat16* __restrict__ A2h, const __nv_bfloat16* __restrict__ A2l,
             const uint4* __restrict__ Wp, const float* __restrict__ bias,
             float* __restrict__ outF,
             __nv_bfloat16* __restrict__ outH, __nv_bfloat16* __restrict__ outL) {
    constexpr int KC    = (KTERM >= 64) ? 64 : KTERM;
    constexpr int NCH   = KTERM / KC;
    constexpr int NP    = 3 * NCH;           // (term, chunk) pairs
    constexpr int RS    = KC + 8;            // bf16 row stride
    constexpr int BUFB  = 64 * RS * 2;       // bytes per buffer
    constexpr int NKS_G = KTERM / 16;
    constexpr int NT    = NOUT / 8;
    constexpr int NTW   = NT / 4;
    constexpr int NV    = 64 * KC / 8;       // uint4 per plane per chunk
    __shared__ __nv_bfloat16 AhS[2][64 * RS];
    __shared__ __nv_bfloat16 AlS[2][64 * RS];

    const int tid = threadIdx.x;
    const int wid = tid >> 5;
    const int lane = tid & 31;
    const int wm = wid & 1;
    const int wn = wid >> 1;
    const int row0 = blockIdx.x * 64;
    const int lrow = lane & 15;
    const int lseg = lane >> 4;

    const uint32_t ah_base = smem_u32(AhS);
    const uint32_t al_base = smem_u32(AlS);
    const __nv_bfloat16* AsH[3] = {A0h, A1h, A2h};
    const __nv_bfloat16* AsL[3] = {A0l, A1l, A2l};

    float acc[2][NTW][4];
    #pragma unroll
    for (int a = 0; a < 2; ++a)
        #pragma unroll
        for (int b = 0; b < NTW; ++b)
            #pragma unroll
            for (int cc = 0; cc < 4; ++cc) acc[a][b][cc] = 0.f;

    auto stage = [&](int buf, int pair) {
        const int term = pair / NCH;
        const int kc0  = (pair % NCH) * KC;
        const __nv_bfloat16* sh = AsH[term] + (size_t)row0 * KTERM + kc0;
        const __nv_bfloat16* sl = AsL[term] + (size_t)row0 * KTERM + kc0;
        #pragma unroll
        for (int it = 0; it < (NV + 255) / 256; ++it) {
            const int idx = tid + it * 256;
            if ((NV % 256 == 0) || idx < NV) {
                const int r  = idx / (KC / 8);
                const int cq = (idx % (KC / 8)) * 8;
                const uint32_t soff = (uint32_t)(buf * BUFB + (r * RS + cq) * 2);
                CP_ASYNC16(ah_base + soff, sh + (size_t)r * KTERM + cq);
                CP_ASYNC16(al_base + soff, sl + (size_t)r * KTERM + cq);
            }
        }
    };

    stage(0, 0);
    CP_COMMIT();

    for (int p = 0; p < NP; ++p) {
        CP_WAIT0();
        __syncthreads();
        if (p + 1 < NP) { stage((p + 1) & 1, p + 1); CP_COMMIT(); }

        const int term = p / NCH;
        const int ks0  = (p % NCH) * (KC / 16);
        const uint4* W = Wp + (size_t)term * NT * NKS_G * 32;
        const int buf = p & 1;
        #pragma unroll
        for (int ks = 0; ks < KC / 16; ++ks) {
            uint32_t ahf[2][4], alf[2][4];
            #pragma unroll
            for (int mt = 0; mt < 2; ++mt) {
                const int row = wm * 32 + mt * 16 + lrow;
                const uint32_t off = (uint32_t)(buf * BUFB + (row * RS + ks * 16) * 2 + lseg * 16);
                ldsm_x4(ahf[mt], ah_base + off);
                ldsm_x4(alf[mt], al_base + off);
            }
            #pragma unroll
            for (int nt = 0; nt < NTW; ++nt) {
                const int ntg = wn * NTW + nt;
                const uint4 b = W[((size_t)ntg * NKS_G + ks0 + ks) * 32 + lane];
                #pragma unroll
                for (int mt = 0; mt < 2; ++mt) {
                    mma_bf16(acc[mt][nt], ahf[mt], b.x, b.y);   // hi @ hi
                    mma_bf16(acc[mt][nt], ahf[mt], b.z, b.w);   // hi @ lo
                    mma_bf16(acc[mt][nt], alf[mt], b.x, b.y);   // lo @ hi
                }
            }
        }
        __syncthreads();
    }

    // epilogue
    const int q  = (lane & 3) * 2;
    const int rr = lane >> 2;
    #pragma unroll
    for (int nt = 0; nt < NTW; ++nt) {
        const int col = wn * NTW * 8 + nt * 8 + q;
        const float bx = bias[col], by = bias[col + 1];
        #pragma unroll
        for (int mt = 0; mt < 2; ++mt) {
            const int r = row0 + wm * 32 + mt * 16 + rr;
            float2 v0 = make_float2(acc[mt][nt][0] + bx, acc[mt][nt][1] + by);
            float2 v1 = make_float2(acc[mt][nt][2] + bx, acc[mt][nt][3] + by);
            if (SPLIT_OUT) {
                uint32_t h0, l0, h1, l1;
                cvt_hilo(v0, h0, l0);
                cvt_hilo(v1, h1, l1);
                *reinterpret_cast<uint32_t*>(outH + (size_t)r * NOUT + col) = h0;
                *reinterpret_cast<uint32_t*>(outL + (size_t)r * NOUT + col) = l0;
                *reinterpret_cast<uint32_t*>(outH + (size_t)(r + 8) * NOUT + col) = h1;
                *reinterpret_cast<uint32_t*>(outL + (size_t)(r + 8) * NOUT + col) = l1;
            } else {
                *reinterpret_cast<float2*>(outF + (size_t)r * NOUT + col) = v0;
                *reinterpret_cast<float2*>(outF + (size_t)(r + 8) * NOUT + col) = v1;
            }
        }
    }
}

// ---------------- pooling + classifier ----------------
__global__ void k_pool(const float* __restrict__ x) {
    int g = blockIdx.x, c = threadIdx.x;
    const float* p = x + (size_t)g * NPG_ * OUTC_ + c;
    float s = 0.f;
    for (int n = 0; n < NPG_; ++n) s += p[n * OUTC_];
    g_gfeat[g * OUTC_ + c] = s * (1.0f / NPG_);
}

__global__ void k_cls(const float* __restrict__ demo,
                      const float* __restrict__ w1, const float* __restrict__ b1,
                      const float* __restrict__ w2, const float* __restrict__ b2,
                      float* __restrict__ out) {
    __shared__ float f[OUTC_ + DEMO_];
    __shared__ float h[MODEL_];
    int g = blockIdx.x, m = threadIdx.x;
    f[m] = g_gfeat[g * OUTC_ + m];
    f[64 + m] = g_gfeat[g * OUTC_ + 64 + m];
    if (m < DEMO_) f[OUTC_ + m] = demo[g * DEMO_ + m];
    __syncthreads();
    float acc = b1[m];
    for (int j = 0; j < OUTC_ + DEMO_; ++j)
        acc = fmaf(f[j], w1[j * MODEL_ + m], acc);
    h[m] = fmaxf(acc, 0.f);
    __syncthreads();
    if (m < 2) {
        float a = b2[m];
        for (int k = 0; k < MODEL_; ++k)
            a = fmaf(h[k], w2[k * 2 + m], a);
        out[g * 2 + m] = a;
    }
}

// ---------------- launcher ----------------
extern "C" void kernel_launch(void* const* d_in, const int* in_sizes, int n_in,
                              void* d_out, int out_size) {
    const int*   node_ids = (const int*)  d_in[0];
    const int*   eidx     = (const int*)  d_in[1];
    const float* eattr    = (const float*)d_in[3];
    const float* demo     = (const float*)d_in[4];
    const float* emb      = (const float*)d_in[5];
    const float* W0       = (const float*)d_in[6];
    const float* b0       = (const float*)d_in[7];
    const float* W1       = (const float*)d_in[8];
    const float* b1c      = (const float*)d_in[9];
    const float* W2       = (const float*)d_in[10];
    const float* b2c      = (const float*)d_in[11];
    const float* cw1      = (const float*)d_in[12];
    const float* cb1      = (const float*)d_in[13];
    const float* cw2      = (const float*)d_in[14];
    const float* cb2      = (const float*)d_in[15];
    float* out = (float*)d_out;

    const int* src = eidx;
    const int* dst = eidx + E_;

    __nv_bfloat16 *x0h, *x0l, *t10h, *t10l, *t20h, *t20l;
    __nv_bfloat16 *xah, *xal, *xbh, *xbl, *t1h, *t1l, *t2h, *t2l;
    float *xc;
    uint4 *wp0, *wp1, *wp2;
    cudaGetSymbolAddress((void**)&x0h,  g_x0h);  cudaGetSymbolAddress((void**)&x0l,  g_x0l);
    cudaGetSymbolAddress((void**)&t10h, g_t10h); cudaGetSymbolAddress((void**)&t10l, g_t10l);
    cudaGetSymbolAddress((void**)&t20h, g_t20h); cudaGetSymbolAddress((void**)&t20l, g_t20l);
    cudaGetSymbolAddress((void**)&xah,  g_xah);  cudaGetSymbolAddress((void**)&xal,  g_xal);
    cudaGetSymbolAddress((void**)&xbh,  g_xbh);  cudaGetSymbolAddress((void**)&xbl,  g_xbl);
    cudaGetSymbolAddress((void**)&t1h,  g_t1h);  cudaGetSymbolAddress((void**)&t1l,  g_t1l);
    cudaGetSymbolAddress((void**)&t2h,  g_t2h);  cudaGetSymbolAddress((void**)&t2l,  g_t2l);
    cudaGetSymbolAddress((void**)&xc,   g_xc);
    cudaGetSymbolAddress((void**)&wp0, g_wp0);
    cudaGetSymbolAddress((void**)&wp1, g_wp1);
    cudaGetSymbolAddress((void**)&wp2, g_wp2);

    const size_t smemEP = 2 * NPG_ * EMB_ * sizeof(float);   // 51.2 KB
    const size_t smemP2 = 2 * NPG_ * 32 * sizeof(float);     // 102.4 KB
    cudaFuncSetAttribute(k_embprop, cudaFuncAttributeMaxDynamicSharedMemorySize, (int)smemEP);
    cudaFuncSetAttribute(k_prop2,   cudaFuncAttributeMaxDynamicSharedMemorySize, (int)smemP2);

    const int WTOT = 2304 + 27648 + 18432;   // 48384

    // 1: preprocessing   2: weight prep   3: embed+props   4: hgemm L0 (ncu capture slot)
    k_pre<<<G_, 512>>>(src, dst, eattr);
    k_wprep_all<<<(WTOT + 255) / 256, 256>>>(W0, W1, W2);
    k_embprop<<<G_, 256, smemEP>>>(node_ids, emb);
    k_hgemm<EMB_, HID_, true><<<N_ / 64, 256>>>(
        x0h, x0l, t10h, t10l, t20h, t20l, wp0, b0, nullptr, xah, xal);

    // layer 1
    k_prop2<<<dim3(G_, HID_ / 32), 256, smemP2>>>(xah, xal, t1h, t1l, t2h, t2l);
    k_hgemm<HID_, HID_, true><<<N_ / 64, 256>>>(
        xah, xal, t1h, t1l, t2h, t2l, wp1, b1c, nullptr, xbh, xbl);

    // layer 2
    k_prop2<<<dim3(G_, HID_ / 32), 256, smemP2>>>(xbh, xbl, t1h, t1l, t2h, t2l);
    k_hgemm<HID_, OUTC_, false><<<N_ / 64, 256>>>(
        xbh, xbl, t1h, t1l, t2h, t2l, wp2, b2c, xc, nullptr, nullptr);

    // pool + classifier
    k_pool<<<G_, OUTC_>>>(xc);
    k_cls<<<G_, MODEL_>>>(demo, cw1, cb1, cw2, cb2, out);
}

// round 10
// speedup vs baseline: 1.9165x; 1.1922x over previous
#include <cuda_runtime.h>
#include <cuda_bf16.h>
#include <cstdint>

// Problem constants
#define G_   64
#define NPG_ 400
#define N_   25600          // G_*NPG_
#define DEG_ 40
#define E_   1024000        // N_*DEG_
#define EMB_ 16
#define HID_ 192
#define OUTC_ 128
#define MODEL_ 64
#define DEMO_ 5

// ---------------- device scratch (no allocations allowed) ----------------
__device__ int   g_rowptr[N_ + 1];
__device__ int2  g_csr[E_];            // .x = src local, .y = norm bits
// split bf16 planes (hi/lo) for all intermediates
__device__ __align__(16) __nv_bfloat16 g_x0h [N_ * EMB_];
__device__ __align__(16) __nv_bfloat16 g_x0l [N_ * EMB_];
__device__ __align__(16) __nv_bfloat16 g_t10h[N_ * EMB_];
__device__ __align__(16) __nv_bfloat16 g_t10l[N_ * EMB_];
__device__ __align__(16) __nv_bfloat16 g_t20h[N_ * EMB_];
__device__ __align__(16) __nv_bfloat16 g_t20l[N_ * EMB_];
__device__ __align__(16) __nv_bfloat16 g_xah [N_ * HID_];
__device__ __align__(16) __nv_bfloat16 g_xal [N_ * HID_];
__device__ __align__(16) __nv_bfloat16 g_xbh [N_ * HID_];
__device__ __align__(16) __nv_bfloat16 g_xbl [N_ * HID_];
__device__ __align__(16) __nv_bfloat16 g_t1h [N_ * HID_];
__device__ __align__(16) __nv_bfloat16 g_t1l [N_ * HID_];
__device__ __align__(16) __nv_bfloat16 g_t2h [N_ * HID_];
__device__ __align__(16) __nv_bfloat16 g_t2l [N_ * HID_];
__device__ float g_xc[N_ * OUTC_];     // final layer output (fp32)
__device__ float g_gfeat[G_ * OUTC_];
// fragment-packed weights: uint4 per (term, n8-tile, k16-step, lane)
__device__ uint4 g_wp0[3 * (HID_  / 8) * (EMB_ / 16) * 32];   // 2304
__device__ uint4 g_wp1[3 * (HID_  / 8) * (HID_ / 16) * 32];   // 27648
__device__ uint4 g_wp2[3 * (OUTC_ / 8) * (HID_ / 16) * 32];   // 18432

// ---------------- helpers ----------------
__device__ __forceinline__ unsigned short bfbits(__nv_bfloat16 h) {
    __nv_bfloat16_raw r = *reinterpret_cast<__nv_bfloat16_raw*>(&h);
    return r.x;
}

__device__ __forceinline__ void cvt_hilo(float2 f, uint32_t& h, uint32_t& l) {
    __nv_bfloat16 h0 = __float2bfloat16(f.x);
    __nv_bfloat16 h1 = __float2bfloat16(f.y);
    __nv_bfloat16 l0 = __float2bfloat16(f.x - __bfloat162float(h0));
    __nv_bfloat16 l1 = __float2bfloat16(f.y - __bfloat162float(h1));
    h = (uint32_t)bfbits(h0) | ((uint32_t)bfbits(h1) << 16);
    l = (uint32_t)bfbits(l0) | ((uint32_t)bfbits(l1) << 16);
}

__device__ __forceinline__ float2 unsplit(uint32_t h, uint32_t l) {
    float2 a = __bfloat1622float2(*reinterpret_cast<__nv_bfloat162*>(&h));
    float2 b = __bfloat1622float2(*reinterpret_cast<__nv_bfloat162*>(&l));
    return make_float2(a.x + b.x, a.y + b.y);
}

__device__ __forceinline__ void mma_bf16(float* c, const uint32_t* a,
                                         uint32_t b0, uint32_t b1) {
    asm volatile(
        "mma.sync.aligned.m16n8k16.row.col.f32.bf16.bf16.f32 "
        "{%0,%1,%2,%3}, {%4,%5,%6,%7}, {%8,%9}, {%0,%1,%2,%3};"
        : "+f"(c[0]), "+f"(c[1]), "+f"(c[2]), "+f"(c[3])
        : "r"(a[0]), "r"(a[1]), "r"(a[2]), "r"(a[3]), "r"(b0), "r"(b1));
}

__device__ __forceinline__ uint32_t smem_u32(const void* p) {
    uint32_t a;
    asm("{ .reg .u64 t; cvta.to.shared.u64 t, %1; cvt.u32.u64 %0, t; }" : "=r"(a) : "l"(p));
    return a;
}

__device__ __forceinline__ void ldsm_x4(uint32_t* r, uint32_t saddr) {
    asm volatile("ldmatrix.sync.aligned.m8n8.x4.shared.b16 {%0,%1,%2,%3}, [%4];"
        : "=r"(r[0]), "=r"(r[1]), "=r"(r[2]), "=r"(r[3]) : "r"(saddr));
}

#define CP_ASYNC16(smem, gptr) \
    asm volatile("cp.async.ca.shared.global [%0], [%1], 16;" \
        :: "r"(smem), "l"(gptr) : "memory")
#define CP_COMMIT() asm volatile("cp.async.commit_group;" ::: "memory")
#define CP_WAIT0()  asm volatile("cp.async.wait_group 0;" ::: "memory")
#define CP_WAIT1()  asm volatile("cp.async.wait_group 1;" ::: "memory")

// ---------------- weight prep helper ----------------
__device__ __forceinline__ void wprep_one(const float* W, int KT, int NO, int idx,
                                          uint4* dst) {
    const int NT = NO / 8, NKS = KT / 16;
    int lane = idx & 31;
    int r = idx >> 5;
    int ks = r % NKS; r /= NKS;
    int ntile = r % NT;
    int t = r / NT;
    int n = ntile * 8 + (lane >> 2);
    int q = (lane & 3) * 2;
    int kb = ks * 16;
    const float* Wt = W + (size_t)t * KT * NO;
    float w0 = Wt[(kb + q + 0) * NO + n];
    float w1 = Wt[(kb + q + 1) * NO + n];
    float w2 = Wt[(kb + q + 8) * NO + n];
    float w3 = Wt[(kb + q + 9) * NO + n];
    uint32_t h01, l01, h23, l23;
    cvt_hilo(make_float2(w0, w1), h01, l01);
    cvt_hilo(make_float2(w2, w3), h23, l23);
    uint4 v; v.x = h01; v.y = h23; v.z = l01; v.w = l23;
    dst[idx] = v;
}

// ---------------- merged per-graph preprocessing + weight prep ----------------
// Blocks [0, G_): graph preprocessing (SMEM atomics).
// Blocks [G_, G_+95): weight fragment packing for all three layers.
__global__ __launch_bounds__(512)
void k_prewprep(const int* __restrict__ src, const int* __restrict__ dst,
                const float* __restrict__ ea,
                const float* __restrict__ W0, const float* __restrict__ W1,
                const float* __restrict__ W2) {
    __shared__ float sdeg[NPG_];
    __shared__ float sdis[NPG_];
    __shared__ int   scnt[NPG_];
    __shared__ int   sscan[NPG_];
    __shared__ int   scur[NPG_];
    const int tid = threadIdx.x;

    if (blockIdx.x >= G_) {
        const int T0 = 3 * (HID_ / 8) * (EMB_ / 16) * 32;    // 2304
        const int T1 = 3 * (HID_ / 8) * (HID_ / 16) * 32;    // 27648
        const int T2 = 3 * (OUTC_ / 8) * (HID_ / 16) * 32;   // 18432
        int idx = (blockIdx.x - G_) * 512 + tid;
        if (idx < T0)                wprep_one(W0, EMB_, HID_,  idx,           g_wp0);
        else if (idx < T0 + T1)      wprep_one(W1, HID_, HID_,  idx - T0,      g_wp1);
        else if (idx < T0 + T1 + T2) wprep_one(W2, HID_, OUTC_, idx - T0 - T1, g_wp2);
        return;
    }

    const int g = blockIdx.x;
    const int eb = g * (NPG_ * DEG_);
    const int nb = g * NPG_;

    if (tid < NPG_) { sdeg[tid] = 0.f; scnt[tid] = 0; }
    __syncthreads();

    for (int e = tid; e < NPG_ * DEG_; e += 512) {
        int s = src[eb + e] - nb;
        int t = dst[eb + e] - nb;
        atomicAdd(&sdeg[s], ea[eb + e]);
        atomicAdd(&scnt[t], 1);
    }
    __syncthreads();

    if (tid < NPG_) {
        float d = sdeg[tid];
        float r = 0.f;
        if (d > 0.f) {
            r = rsqrtf(d);
            r = r * (1.5f - 0.5f * d * r * r);
        }
        sdis[tid] = r;
        sscan[tid] = scnt[tid];
    }
    __syncthreads();

    for (int off = 1; off < NPG_; off <<= 1) {
        int x = 0;
        if (tid < NPG_ && tid >= off) x = sscan[tid - off];
        __syncthreads();
        if (tid < NPG_) sscan[tid] += x;
        __syncthreads();
    }
    if (tid < NPG_) {
        int excl = eb + sscan[tid] - scnt[tid];
        g_rowptr[nb + tid] = excl;
        scur[tid] = excl;
    }
    if (g == 0 && tid == 0) g_rowptr[N_] = E_;
    __syncthreads();

    for (int e = tid; e < NPG_ * DEG_; e += 512) {
        int s = src[eb + e] - nb;
        int t = dst[eb + e] - nb;
        float w = -sdis[s] * ea[eb + e] * sdis[t];
        int p = atomicAdd(&scur[t], 1);
        g_csr[p] = make_int2(s, __float_as_int(w));
    }
}

// ---------------- fused embed + both d=16 props, split-plane outputs ----------------
__global__ __launch_bounds__(512)
void k_embprop(const int* __restrict__ ids, const float* __restrict__ emb) {
    extern __shared__ float sm[];
    float* x0s = sm;                 // 400*16
    float* t1s = sm + NPG_ * EMB_;   // 400*16
    const int g = blockIdx.x, tid = threadIdx.x;
    const int nb = g * NPG_;

    for (int i = tid; i < NPG_ * EMB_; i += 512) {
        int n = i >> 4, c = i & 15;
        x0s[i] = emb[ids[nb + n] * EMB_ + c];
    }
    __syncthreads();

    // write x0 split planes
    for (int i2 = tid; i2 < NPG_ * (EMB_ / 2); i2 += 512) {
        int n = i2 >> 3, cp = (i2 & 7) * 2;
        uint32_t h, l;
        cvt_hilo(make_float2(x0s[n * EMB_ + cp], x0s[n * EMB_ + cp + 1]), h, l);
        *reinterpret_cast<uint32_t*>(&g_x0h[(size_t)(nb + n) * EMB_ + cp]) = h;
        *reinterpret_cast<uint32_t*>(&g_x0l[(size_t)(nb + n) * EMB_ + cp]) = l;
    }

    const int sub = tid & 7;          // 8 lanes per node (2 ch each)
    const int n0  = tid >> 3;         // 64 node groups
    const int c   = sub * 2;

    // t1 = P x0
    for (int n = n0; n < NPG_; n += 64) {
        int beg = g_rowptr[nb + n], end = g_rowptr[nb + n + 1];
        float ax = 0.f, ay = 0.f;
        for (int e = beg; e < end; ++e) {
            int2 p = g_csr[e];
            float w = __int_as_float(p.y);
            ax = fmaf(w, x0s[p.x * EMB_ + c], ax);
            ay = fmaf(w, x0s[p.x * EMB_ + c + 1], ay);
        }
        t1s[n * EMB_ + c] = ax;  t1s[n * EMB_ + c + 1] = ay;
        uint32_t h, l;
        cvt_hilo(make_float2(ax, ay), h, l);
        *reinterpret_cast<uint32_t*>(&g_t10h[(size_t)(nb + n) * EMB_ + c]) = h;
        *reinterpret_cast<uint32_t*>(&g_t10l[(size_t)(nb + n) * EMB_ + c]) = l;
    }
    __syncthreads();

    // t2 = 2 P t1 - x0
    for (int n = n0; n < NPG_; n += 64) {
        int beg = g_rowptr[nb + n], end = g_rowptr[nb + n + 1];
        float ax = 0.f, ay = 0.f;
        for (int e = beg; e < end; ++e) {
            int2 p = g_csr[e];
            float w = __int_as_float(p.y);
            ax = fmaf(w, t1s[p.x * EMB_ + c], ax);
            ay = fmaf(w, t1s[p.x * EMB_ + c + 1], ay);
        }
        float ox = 2.f * ax - x0s[n * EMB_ + c];
        float oy = 2.f * ay - x0s[n * EMB_ + c + 1];
        uint32_t h, l;
        cvt_hilo(make_float2(ox, oy), h, l);
        *reinterpret_cast<uint32_t*>(&g_t20h[(size_t)(nb + n) * EMB_ + c]) = h;
        *reinterpret_cast<uint32_t*>(&g_t20l[(size_t)(nb + n) * EMB_ + c]) = l;
    }
}

// ---------------- fused prop pair (t1 and t2) on 32-channel chunks ----------------
// 512 threads: 32 node-groups x 16 lanes (2 ch per lane).
__global__ __launch_bounds__(512, 1)
void k_prop2(const __nv_bfloat16* __restrict__ hH, const __nv_bfloat16* __restrict__ hL,
             __nv_bfloat16* __restrict__ t1H, __nv_bfloat16* __restrict__ t1L,
             __nv_bfloat16* __restrict__ t2H, __nv_bfloat16* __restrict__ t2L) {
    extern __shared__ float sm[];
    float* hs  = sm;                 // 400*32
    float* t1s = sm + NPG_ * 32;     // 400*32
    const int g  = blockIdx.x;
    const int cb = blockIdx.y * 32;
    const int tid = threadIdx.x;
    const int nb = g * NPG_;

    // stage h chunk (hi+lo -> fp32)
    for (int i = tid; i < NPG_ * 4; i += 512) {    // 8 values per i
        int n = i >> 2, c = (i & 3) * 8;
        const uint4 hv = *reinterpret_cast<const uint4*>(hH + (size_t)(nb + n) * HID_ + cb + c);
        const uint4 lv = *reinterpret_cast<const uint4*>(hL + (size_t)(nb + n) * HID_ + cb + c);
        const uint32_t* hw = reinterpret_cast<const uint32_t*>(&hv);
        const uint32_t* lw = reinterpret_cast<const uint32_t*>(&lv);
        #pragma unroll
        for (int j = 0; j < 4; ++j) {
            float2 f = unsplit(hw[j], lw[j]);
            hs[n * 32 + c + 2 * j]     = f.x;
            hs[n * 32 + c + 2 * j + 1] = f.y;
        }
    }
    __syncthreads();

    const int sub = tid & 15;         // 16 lanes per node
    const int grp = tid >> 4;         // 32 node groups
    const int c   = sub * 2;

    // t1 = P h
    for (int n = grp; n < NPG_; n += 32) {
        const int beg = g_rowptr[nb + n];
        const int end = g_rowptr[nb + n + 1];
        float ax = 0.f, ay = 0.f;
        int e = beg;
        for (; e + 2 <= end; e += 2) {
            int2 p0 = g_csr[e];
            int2 p1 = g_csr[e + 1];
            float w0 = __int_as_float(p0.y);
            float w1 = __int_as_float(p1.y);
            float2 h0 = *reinterpret_cast<const float2*>(&hs[p0.x * 32 + c]);
            float2 h1 = *reinterpret_cast<const float2*>(&hs[p1.x * 32 + c]);
            ax = fmaf(w0, h0.x, ax);  ay = fmaf(w0, h0.y, ay);
            ax = fmaf(w1, h1.x, ax);  ay = fmaf(w1, h1.y, ay);
        }
        for (; e < end; ++e) {
            int2 p = g_csr[e];
            float w = __int_as_float(p.y);
            float2 hv = *reinterpret_cast<const float2*>(&hs[p.x * 32 + c]);
            ax = fmaf(w, hv.x, ax);  ay = fmaf(w, hv.y, ay);
        }
        t1s[n * 32 + c] = ax;  t1s[n * 32 + c + 1] = ay;
        uint32_t h, l;
        cvt_hilo(make_float2(ax, ay), h, l);
        *reinterpret_cast<uint32_t*>(t1H + (size_t)(nb + n) * HID_ + cb + c) = h;
        *reinterpret_cast<uint32_t*>(t1L + (size_t)(nb + n) * HID_ + cb + c) = l;
    }
    __syncthreads();

    // t2 = 2 P t1 - h
    for (int n = grp; n < NPG_; n += 32) {
        const int beg = g_rowptr[nb + n];
        const int end = g_rowptr[nb + n + 1];
        float ax = 0.f, ay = 0.f;
        int e = beg;
        for (; e + 2 <= end; e += 2) {
            int2 p0 = g_csr[e];
            int2 p1 = g_csr[e + 1];
            float w0 = __int_as_float(p0.y);
            float w1 = __int_as_float(p1.y);
            float2 h0 = *reinterpret_cast<const float2*>(&t1s[p0.x * 32 + c]);
            float2 h1 = *reinterpret_cast<const float2*>(&t1s[p1.x * 32 + c]);
            ax = fmaf(w0, h0.x, ax);  ay = fmaf(w0, h0.y, ay);
            ax = fmaf(w1, h1.x, ax);  ay = fmaf(w1, h1.y, ay);
        }
        for (; e < end; ++e) {
            int2 p = g_csr[e];
            float w = __int_as_float(p.y);
            float2 hv = *reinterpret_cast<const float2*>(&t1s[p.x * 32 + c]);
            ax = fmaf(w, hv.x, ax);  ay = fmaf(w, hv.y, ay);
        }
        float ox = 2.f * ax - hs[n * 32 + c];
        float oy = 2.f * ay - hs[n * 32 + c + 1];
        uint32_t h, l;
        cvt_hilo(make_float2(ox, oy), h, l);
        *reinterpret_cast<uint32_t*>(t2H + (size_t)(nb + n) * HID_ + cb + c) = h;
        *reinterpret_cast<uint32_t*>(t2L + (size_t)(nb + n) * HID_ + cb + c) = l;
    }
}

// ---------------- HMMA fused layer GEMM v4 ----------------
// 3-deep cp.async ring, ONE __syncthreads per chunk. Split-plane inputs.
// 64-row CTA tile; 8 warps = 2 row-warps x 4 col-warps; 2 CTAs/SM.
template <int KTERM, int NOUT, bool SPLIT_OUT>
__global__ __launch_bounds__(256, 2)
void k_hgemm(const __nv_bfloat16* __restrict__ A0h, const __nv_bfloat16* __restrict__ A0l,
             const __nv_bfloat16* __restrict__ A1h, const __nv_bfloat16* __restrict__ A1l,
             const __nv_bfloat16* __restrict__ A2h, const __nv_bfloat16* __restrict__ A2l,
             const uint4* __restrict__ Wp, const float* __restrict__ bias,
             float* __restrict__ outF,
             __nv_bfloat16* __restrict__ outH, __nv_bfloat16* __restrict__ outL) {
    constexpr int KC    = (KTERM >= 64) ? 64 : KTERM;
    constexpr int NCH   = KTERM / KC;
    constexpr int NP    = 3 * NCH;           // (term, chunk) pairs
    constexpr int RS    = KC + 8;            // bf16 row stride
    constexpr int BUFB  = 64 * RS * 2;       // bytes per buffer
    constexpr int NKS_G = KTERM / 16;
    constexpr int NT    = NOUT / 8;
    constexpr int NTW   = NT / 4;
    constexpr int NV    = 64 * KC / 8;       // uint4 per plane per chunk
    __shared__ __nv_bfloat16 AhS[3][64 * RS];
    __shared__ __nv_bfloat16 AlS[3][64 * RS];

    const int tid = threadIdx.x;
    const int wid = tid >> 5;
    const int lane = tid & 31;
    const int wm = wid & 1;
    const int wn = wid >> 1;
    const int row0 = blockIdx.x * 64;
    const int lrow = lane & 15;
    const int lseg = lane >> 4;

    const uint32_t ah_base = smem_u32(AhS);
    const uint32_t al_base = smem_u32(AlS);
    const __nv_bfloat16* AsH[3] = {A0h, A1h, A2h};
    const __nv_bfloat16* AsL[3] = {A0l, A1l, A2l};

    float acc[2][NTW][4];
    #pragma unroll
    for (int a = 0; a < 2; ++a)
        #pragma unroll
        for (int b = 0; b < NTW; ++b)
            #pragma unroll
            for (int cc = 0; cc < 4; ++cc) acc[a][b][cc] = 0.f;

    auto stage = [&](int buf, int pair) {
        const int term = pair / NCH;
        const int kc0  = (pair % NCH) * KC;
        const __nv_bfloat16* sh = AsH[term] + (size_t)row0 * KTERM + kc0;
        const __nv_bfloat16* sl = AsL[term] + (size_t)row0 * KTERM + kc0;
        #pragma unroll
        for (int it = 0; it < (NV + 255) / 256; ++it) {
            const int idx = tid + it * 256;
            if ((NV % 256 == 0) || idx < NV) {
                const int r  = idx / (KC / 8);
                const int cq = (idx % (KC / 8)) * 8;
                const uint32_t soff = (uint32_t)(buf * BUFB + (r * RS + cq) * 2);
                CP_ASYNC16(ah_base + soff, sh + (size_t)r * KTERM + cq);
                CP_ASYNC16(al_base + soff, sl + (size_t)r * KTERM + cq);
            }
        }
        CP_COMMIT();
    };

    stage(0, 0);
    if (NP > 1) stage(1, 1);

    for (int p = 0; p < NP; ++p) {
        if (p == NP - 1) { CP_WAIT0(); } else { CP_WAIT1(); }
        __syncthreads();
        if (p + 2 < NP) stage((p + 2) % 3, p + 2);

        const int term = p / NCH;
        const int ks0  = (p % NCH) * (KC / 16);
        const uint4* W = Wp + (size_t)term * NT * NKS_G * 32;
        const int buf = p % 3;
        #pragma unroll
        for (int ks = 0; ks < KC / 16; ++ks) {
            uint32_t ahf[2][4], alf[2][4];
            #pragma unroll
            for (int mt = 0; mt < 2; ++mt) {
                const int row = wm * 32 + mt * 16 + lrow;
                const uint32_t off = (uint32_t)(buf * BUFB + (row * RS + ks * 16) * 2 + lseg * 16);
                ldsm_x4(ahf[mt], ah_base + off);
                ldsm_x4(alf[mt], al_base + off);
            }
            #pragma unroll
            for (int nt = 0; nt < NTW; ++nt) {
                const int ntg = wn * NTW + nt;
                const uint4 b = W[((size_t)ntg * NKS_G + ks0 + ks) * 32 + lane];
                #pragma unroll
                for (int mt = 0; mt < 2; ++mt) {
                    mma_bf16(acc[mt][nt], ahf[mt], b.x, b.y);   // hi @ hi
                    mma_bf16(acc[mt][nt], ahf[mt], b.z, b.w);   // hi @ lo
                    mma_bf16(acc[mt][nt], alf[mt], b.x, b.y);   // lo @ hi
                }
            }
        }
    }

    // epilogue
    const int q  = (lane & 3) * 2;
    const int rr = lane >> 2;
    #pragma unroll
    for (int nt = 0; nt < NTW; ++nt) {
        const int col = wn * NTW * 8 + nt * 8 + q;
        const float bx = bias[col], by = bias[col + 1];
        #pragma unroll
        for (int mt = 0; mt < 2; ++mt) {
            const int r = row0 + wm * 32 + mt * 16 + rr;
            float2 v0 = make_float2(acc[mt][nt][0] + bx, acc[mt][nt][1] + by);
            float2 v1 = make_float2(acc[mt][nt][2] + bx, acc[mt][nt][3] + by);
            if (SPLIT_OUT) {
                uint32_t h0, l0, h1, l1;
                cvt_hilo(v0, h0, l0);
                cvt_hilo(v1, h1, l1);
                *reinterpret_cast<uint32_t*>(outH + (size_t)r * NOUT + col) = h0;
                *reinterpret_cast<uint32_t*>(outL + (size_t)r * NOUT + col) = l0;
                *reinterpret_cast<uint32_t*>(outH + (size_t)(r + 8) * NOUT + col) = h1;
                *reinterpret_cast<uint32_t*>(outL + (size_t)(r + 8) * NOUT + col) = l1;
            } else {
                *reinterpret_cast<float2*>(outF + (size_t)r * NOUT + col) = v0;
                *reinterpret_cast<float2*>(outF + (size_t)(r + 8) * NOUT + col) = v1;
            }
        }
    }
}

// ---------------- pooling + classifier ----------------
__global__ void k_pool(const float* __restrict__ x) {
    int g = blockIdx.x, c = threadIdx.x;
    const float* p = x + (size_t)g * NPG_ * OUTC_ + c;
    float s = 0.f;
    for (int n = 0; n < NPG_; ++n) s += p[n * OUTC_];
    g_gfeat[g * OUTC_ + c] = s * (1.0f / NPG_);
}

__global__ void k_cls(const float* __restrict__ demo,
                      const float* __restrict__ w1, const float* __restrict__ b1,
                      const float* __restrict__ w2, const float* __restrict__ b2,
                      float* __restrict__ out) {
    __shared__ float f[OUTC_ + DEMO_];
    __shared__ float h[MODEL_];
    int g = blockIdx.x, m = threadIdx.x;
    f[m] = g_gfeat[g * OUTC_ + m];
    f[64 + m] = g_gfeat[g * OUTC_ + 64 + m];
    if (m < DEMO_) f[OUTC_ + m] = demo[g * DEMO_ + m];
    __syncthreads();
    float acc = b1[m];
    for (int j = 0; j < OUTC_ + DEMO_; ++j)
        acc = fmaf(f[j], w1[j * MODEL_ + m], acc);
    h[m] = fmaxf(acc, 0.f);
    __syncthreads();
    if (m < 2) {
        float a = b2[m];
        for (int k = 0; k < MODEL_; ++k)
            a = fmaf(h[k], w2[k * 2 + m], a);
        out[g * 2 + m] = a;
    }
}

// ---------------- launcher ----------------
extern "C" void kernel_launch(void* const* d_in, const int* in_sizes, int n_in,
                              void* d_out, int out_size) {
    const int*   node_ids = (const int*)  d_in[0];
    const int*   eidx     = (const int*)  d_in[1];
    const float* eattr    = (const float*)d_in[3];
    const float* demo     = (const float*)d_in[4];
    const float* emb      = (const float*)d_in[5];
    const float* W0       = (const float*)d_in[6];
    const float* b0       = (const float*)d_in[7];
    const float* W1       = (const float*)d_in[8];
    const float* b1c      = (const float*)d_in[9];
    const float* W2       = (const float*)d_in[10];
    const float* b2c      = (const float*)d_in[11];
    const float* cw1      = (const float*)d_in[12];
    const float* cb1      = (const float*)d_in[13];
    const float* cw2      = (const float*)d_in[14];
    const float* cb2      = (const float*)d_in[15];
    float* out = (float*)d_out;

    const int* src = eidx;
    const int* dst = eidx + E_;

    __nv_bfloat16 *x0h, *x0l, *t10h, *t10l, *t20h, *t20l;
    __nv_bfloat16 *xah, *xal, *xbh, *xbl, *t1h, *t1l, *t2h, *t2l;
    float *xc;
    uint4 *wp0, *wp1, *wp2;
    cudaGetSymbolAddress((void**)&x0h,  g_x0h);  cudaGetSymbolAddress((void**)&x0l,  g_x0l);
    cudaGetSymbolAddress((void**)&t10h, g_t10h); cudaGetSymbolAddress((void**)&t10l, g_t10l);
    cudaGetSymbolAddress((void**)&t20h, g_t20h); cudaGetSymbolAddress((void**)&t20l, g_t20l);
    cudaGetSymbolAddress((void**)&xah,  g_xah);  cudaGetSymbolAddress((void**)&xal,  g_xal);
    cudaGetSymbolAddress((void**)&xbh,  g_xbh);  cudaGetSymbolAddress((void**)&xbl,  g_xbl);
    cudaGetSymbolAddress((void**)&t1h,  g_t1h);  cudaGetSymbolAddress((void**)&t1l,  g_t1l);
    cudaGetSymbolAddress((void**)&t2h,  g_t2h);  cudaGetSymbolAddress((void**)&t2l,  g_t2l);
    cudaGetSymbolAddress((void**)&xc,   g_xc);
    cudaGetSymbolAddress((void**)&wp0, g_wp0);
    cudaGetSymbolAddress((void**)&wp1, g_wp1);
    cudaGetSymbolAddress((void**)&wp2, g_wp2);

    const size_t smemEP = 2 * NPG_ * EMB_ * sizeof(float);   // 51.2 KB
    const size_t smemP2 = 2 * NPG_ * 32 * sizeof(float);     // 102.4 KB
    cudaFuncSetAttribute(k_embprop, cudaFuncAttributeMaxDynamicSharedMemorySize, (int)smemEP);
    cudaFuncSetAttribute(k_prop2,   cudaFuncAttributeMaxDynamicSharedMemorySize, (int)smemP2);

    const int WTOT = 2304 + 27648 + 18432;          // 48384
    const int WBLK = (WTOT + 511) / 512;            // 95

    // 1: pre+wprep   2: embed+props   3: hgemm L0   4: prop2 L1 (ncu slot)
    k_prewprep<<<G_ + WBLK, 512>>>(src, dst, eattr, W0, W1, W2);
    k_embprop<<<G_, 512, smemEP>>>(node_ids, emb);
    k_hgemm<EMB_, HID_, true><<<N_ / 64, 256>>>(
        x0h, x0l, t10h, t10l, t20h, t20l, wp0, b0, nullptr, xah, xal);

    // layer 1
    k_prop2<<<dim3(G_, HID_ / 32), 512, smemP2>>>(xah, xal, t1h, t1l, t2h, t2l);
    k_hgemm<HID_, HID_, true><<<N_ / 64, 256>>>(
        xah, xal, t1h, t1l, t2h, t2l, wp1, b1c, nullptr, xbh, xbl);

    // layer 2
    k_prop2<<<dim3(G_, HID_ / 32), 512, smemP2>>>(xbh, xbl, t1h, t1l, t2h, t2l);
    k_hgemm<HID_, OUTC_, false><<<N_ / 64, 256>>>(
        xbh, xbl, t1h, t1l, t2h, t2l, wp2, b2c, xc, nullptr, nullptr);

    // pool + classifier
    k_pool<<<G_, OUTC_>>>(xc);
    k_cls<<<G_, MODEL_>>>(demo, cw1, cb1, cw2, cb2, out);
}